// round 4
// baseline (speedup 1.0000x reference)
#include <cuda_runtime.h>
#include <cuda_bf16.h>
#include <math.h>

#define N_NODES 50000
#define NE      1600000
#define NT      (NE + N_NODES)     // edges + self loops
#define HH      4
#define CC      32
#define FF      128                // HH*CC
#define NEG_SLOPE 0.2f

// ---------------- scratch (device globals; no allocations allowed) ----------------
__device__ float  g_xp[N_NODES * FF];       // projected features  [N,128]
__device__ float  g_asrc[N_NODES * 4];
__device__ float  g_adst[N_NODES * 4];
__device__ float  g_easum[N_NODES * 7];
__device__ int    g_deg[N_NODES];
__device__ int    g_rowptr[N_NODES + 1];
__device__ int    g_wptr[N_NODES];
__device__ int    g_csrc[NT];
__device__ float4 g_calpha[NT];
__device__ float  g_aloop[N_NODES * 4];
__device__ float  g_h[N_NODES * FF];        // ELU(out+bias) hidden
__device__ float  g_M[7 * 4];               // folded edge attention matrix
__device__ int    g_is64;                   // edge_index dtype flag

__device__ __forceinline__ float lrelu(float v) { return v > 0.f ? v : NEG_SLOPE * v; }

// index accessor that works for both int32 and int64 edge_index
__device__ __forceinline__ int ld_idx(const void* ei, int pos) {
    if (g_is64) return (int)((const long long*)ei)[pos];
    return ((const int*)ei)[pos];
}

// ---------------- K-1: detect edge_index dtype ----------------
// int64 little-endian values < 2^31 have zero high words at odd 32-bit offsets.
__global__ void k_detect(const int* __restrict__ ei_w) {
    __shared__ int ok[2];
    int t = threadIdx.x;
    int v = ei_w[2 * t + 1];
    unsigned ball = __ballot_sync(0xFFFFFFFFu, v == 0);
    if ((t & 31) == 0) ok[t >> 5] = (ball == 0xFFFFFFFFu) ? 1 : 0;
    __syncthreads();
    if (t == 0) g_is64 = ok[0] & ok[1];
}

// ---------------- K0: zero counters ----------------
__global__ void k_zero() {
    int t = blockIdx.x * blockDim.x + threadIdx.x;
    if (t < N_NODES) g_deg[t] = 0;
    if (t < 7 * N_NODES) g_easum[t] = 0.f;
}

// ---------------- K1: in-degree + edge_attr segment sum ----------------
__global__ void k_deg(const void* __restrict__ ei, const float* __restrict__ ea) {
    int e = blockIdx.x * blockDim.x + threadIdx.x;
    if (e >= NE) return;
    int dst = ld_idx(ei, NE + e);
    atomicAdd(&g_deg[dst], 1);
#pragma unroll
    for (int k = 0; k < 7; k++) atomicAdd(&g_easum[dst * 7 + k], ea[e * 7 + k]);
}

// ---------------- K2: fold W_edge with att_edge -> M[7][4] ----------------
__global__ void k_foldM(const float* __restrict__ W_edge, const float* __restrict__ att_edge) {
    int t = threadIdx.x;
    if (t < 28) {
        int k = t >> 2, h = t & 3;
        float s = 0.f;
        for (int c = 0; c < CC; c++) s += W_edge[k * FF + h * CC + c] * att_edge[h * CC + c];
        g_M[k * 4 + h] = s;
    }
}

// ---------------- K3: per-node projection, a_src/a_dst, self-loop alpha ----------------
__global__ void k_node(const float* __restrict__ x, const float* __restrict__ W_gat,
                       const float* __restrict__ att_src, const float* __restrict__ att_dst) {
    int warp = (blockIdx.x * blockDim.x + threadIdx.x) >> 5;
    int lane = threadIdx.x & 31;
    if (warp >= N_NODES) return;
    int n = warp;
    float x0 = x[n * 3 + 0], x1 = x[n * 3 + 1], x2 = x[n * 3 + 2];
    int i0 = lane * 4;
    float v[4];
    float as = 0.f, ad = 0.f;
#pragma unroll
    for (int j = 0; j < 4; j++) {
        int i = i0 + j;
        float p = fmaf(x0, W_gat[i], fmaf(x1, W_gat[FF + i], x2 * W_gat[2 * FF + i]));
        v[j] = p;
        as = fmaf(p, att_src[i], as);
        ad = fmaf(p, att_dst[i], ad);
    }
    *(float4*)&g_xp[n * FF + i0] = make_float4(v[0], v[1], v[2], v[3]);
    // reduce within each 8-lane group (one group per head)
#pragma unroll
    for (int o = 1; o < 8; o <<= 1) {
        as += __shfl_xor_sync(0xFFFFFFFFu, as, o);
        ad += __shfl_xor_sync(0xFFFFFFFFu, ad, o);
    }
    int h = lane >> 3;
    if ((lane & 7) == 0) {
        g_asrc[n * 4 + h] = as;
        g_adst[n * 4 + h] = ad;
    }
    // self loop alpha (pre-softmax), lanes 0..3 compute head=lane
    float asum_h = __shfl_sync(0xFFFFFFFFu, as + ad, (lane & 3) * 8);
    if (lane < 4) {
        int hh = lane;
        float invd = 1.0f / fmaxf((float)g_deg[n], 1.0f);
        float ae = 0.f;
#pragma unroll
        for (int k = 0; k < 7; k++) ae = fmaf(g_easum[n * 7 + k] * invd, g_M[k * 4 + hh], ae);
        g_aloop[n * 4 + hh] = lrelu(asum_h + ae);
    }
}

// ---------------- K4: exclusive scan of (deg+1) -> row_ptr, wptr ----------------
__global__ void k_scan() {
    __shared__ int wsum[32];
    __shared__ int s_carry;
    int t = threadIdx.x, lane = t & 31, w = t >> 5;
    if (t == 0) s_carry = 0;
    __syncthreads();
    for (int base = 0; base < N_NODES; base += 1024) {
        int i = base + t;
        int v = (i < N_NODES) ? (g_deg[i] + 1) : 0;
        int s = v;
#pragma unroll
        for (int o = 1; o < 32; o <<= 1) {
            int u = __shfl_up_sync(0xFFFFFFFFu, s, o);
            if (lane >= o) s += u;
        }
        if (lane == 31) wsum[w] = s;
        __syncthreads();
        if (w == 0) {
            int ws = wsum[lane];
#pragma unroll
            for (int o = 1; o < 32; o <<= 1) {
                int u = __shfl_up_sync(0xFFFFFFFFu, ws, o);
                if (lane >= o) ws += u;
            }
            wsum[lane] = ws;
        }
        __syncthreads();
        int excl = s_carry + (w > 0 ? wsum[w - 1] : 0) + s - v;
        if (i < N_NODES) { g_rowptr[i] = excl; g_wptr[i] = excl; }
        int total = wsum[31];
        __syncthreads();
        if (t == 0) s_carry += total;
        __syncthreads();
    }
    if (t == 0) g_rowptr[N_NODES] = s_carry;
}

// ---------------- K5: per-edge alpha + CSR scatter (incl. self loops) ----------------
__global__ void k_edge(const void* __restrict__ ei, const float* __restrict__ ea) {
    int t = blockIdx.x * blockDim.x + threadIdx.x;
    if (t >= NT) return;
    int src, dst;
    float4 a4;
    if (t < NE) {
        src = ld_idx(ei, t);
        dst = ld_idx(ei, NE + t);
        float e[7];
#pragma unroll
        for (int k = 0; k < 7; k++) e[k] = ea[t * 7 + k];
        float ah[4];
#pragma unroll
        for (int h = 0; h < 4; h++) {
            float s = 0.f;
#pragma unroll
            for (int k = 0; k < 7; k++) s = fmaf(e[k], g_M[k * 4 + h], s);
            ah[h] = s;
        }
        float4 as = *(const float4*)&g_asrc[src * 4];
        float4 ad = *(const float4*)&g_adst[dst * 4];
        a4.x = lrelu(as.x + ad.x + ah[0]);
        a4.y = lrelu(as.y + ad.y + ah[1]);
        a4.z = lrelu(as.z + ad.z + ah[2]);
        a4.w = lrelu(as.w + ad.w + ah[3]);
    } else {
        int n = t - NE;
        src = n; dst = n;
        a4 = *(const float4*)&g_aloop[n * 4];
    }
    int pos = atomicAdd(&g_wptr[dst], 1);
    g_csrc[pos] = src;
    g_calpha[pos] = a4;
}

// ---------------- K6: per-node softmax + weighted aggregation (warp/node) ----------------
__global__ void k_agg(const float* __restrict__ bias) {
    int warp = (blockIdx.x * blockDim.x + threadIdx.x) >> 5;
    int lane = threadIdx.x & 31;
    if (warp >= N_NODES) return;
    int n = warp;
    int rs = g_rowptr[n], re = g_rowptr[n + 1];

    // pass A: component-wise max (per head)
    float4 m4 = make_float4(-1e30f, -1e30f, -1e30f, -1e30f);
    for (int i = rs + lane; i < re; i += 32) {
        float4 a = g_calpha[i];
        m4.x = fmaxf(m4.x, a.x); m4.y = fmaxf(m4.y, a.y);
        m4.z = fmaxf(m4.z, a.z); m4.w = fmaxf(m4.w, a.w);
    }
#pragma unroll
    for (int o = 16; o > 0; o >>= 1) {
        m4.x = fmaxf(m4.x, __shfl_xor_sync(0xFFFFFFFFu, m4.x, o));
        m4.y = fmaxf(m4.y, __shfl_xor_sync(0xFFFFFFFFu, m4.y, o));
        m4.z = fmaxf(m4.z, __shfl_xor_sync(0xFFFFFFFFu, m4.z, o));
        m4.w = fmaxf(m4.w, __shfl_xor_sync(0xFFFFFFFFu, m4.w, o));
    }
    // pass B: exp-sum
    float4 d4 = make_float4(0.f, 0.f, 0.f, 0.f);
    for (int i = rs + lane; i < re; i += 32) {
        float4 a = g_calpha[i];
        d4.x += __expf(a.x - m4.x); d4.y += __expf(a.y - m4.y);
        d4.z += __expf(a.z - m4.z); d4.w += __expf(a.w - m4.w);
    }
#pragma unroll
    for (int o = 16; o > 0; o >>= 1) {
        d4.x += __shfl_xor_sync(0xFFFFFFFFu, d4.x, o);
        d4.y += __shfl_xor_sync(0xFFFFFFFFu, d4.y, o);
        d4.z += __shfl_xor_sync(0xFFFFFFFFu, d4.z, o);
        d4.w += __shfl_xor_sync(0xFFFFFFFFu, d4.w, o);
    }
    int h = lane >> 3;
    float mh  = (h == 0) ? m4.x : (h == 1) ? m4.y : (h == 2) ? m4.z : m4.w;
    float dh  = (h == 0) ? d4.x : (h == 1) ? d4.y : (h == 2) ? d4.z : d4.w;
    float ih  = 1.0f / dh;

    const float* abase = (const float*)g_calpha;
    float4 acc = make_float4(0.f, 0.f, 0.f, 0.f);
    int i = rs;
    // unroll by 4 for MLP on the gather chain
    for (; i + 4 <= re; i += 4) {
        int s0 = g_csrc[i + 0], s1 = g_csrc[i + 1], s2 = g_csrc[i + 2], s3 = g_csrc[i + 3];
        float w0 = __expf(abase[(i + 0) * 4 + h] - mh) * ih;
        float w1 = __expf(abase[(i + 1) * 4 + h] - mh) * ih;
        float w2 = __expf(abase[(i + 2) * 4 + h] - mh) * ih;
        float w3 = __expf(abase[(i + 3) * 4 + h] - mh) * ih;
        float4 v0 = *(const float4*)&g_xp[s0 * FF + lane * 4];
        float4 v1 = *(const float4*)&g_xp[s1 * FF + lane * 4];
        float4 v2 = *(const float4*)&g_xp[s2 * FF + lane * 4];
        float4 v3 = *(const float4*)&g_xp[s3 * FF + lane * 4];
        acc.x += w0 * v0.x + w1 * v1.x + w2 * v2.x + w3 * v3.x;
        acc.y += w0 * v0.y + w1 * v1.y + w2 * v2.y + w3 * v3.y;
        acc.z += w0 * v0.z + w1 * v1.z + w2 * v2.z + w3 * v3.z;
        acc.w += w0 * v0.w + w1 * v1.w + w2 * v2.w + w3 * v3.w;
    }
    for (; i < re; i++) {
        int s0 = g_csrc[i];
        float w0 = __expf(abase[i * 4 + h] - mh) * ih;
        float4 v0 = *(const float4*)&g_xp[s0 * FF + lane * 4];
        acc.x += w0 * v0.x; acc.y += w0 * v0.y;
        acc.z += w0 * v0.z; acc.w += w0 * v0.w;
    }
    // ELU(out + bias)
    float4 b = *(const float4*)&bias[lane * 4];
    float r0 = acc.x + b.x, r1 = acc.y + b.y, r2 = acc.z + b.z, r3 = acc.w + b.w;
    r0 = r0 > 0.f ? r0 : expm1f(r0);
    r1 = r1 > 0.f ? r1 : expm1f(r1);
    r2 = r2 > 0.f ? r2 : expm1f(r2);
    r3 = r3 > 0.f ? r3 : expm1f(r3);
    *(float4*)&g_h[n * FF + lane * 4] = make_float4(r0, r1, r2, r3);
}

// ---------------- K7: fused MLP  (h@W1+b1 -> PReLU -> @W2+b2) ----------------
#define MLP_SMEM (128 * 128 * 4 + 128 * 32 * 4 + 64 * 129 * 4)
__global__ void k_mlp(const float* __restrict__ W1, const float* __restrict__ b1,
                      const float* __restrict__ pa, const float* __restrict__ W2,
                      const float* __restrict__ b2, float* __restrict__ out) {
    extern __shared__ float smem[];
    float* sW1 = smem;                 // [128][128]
    float* sW2 = sW1 + 128 * 128;      // [128][32]
    float* sh  = sW2 + 128 * 32;       // [64][129]
    int t = threadIdx.x;
    for (int i = t; i < 128 * 128; i += 256) sW1[i] = W1[i];
    for (int i = t; i < 128 * 32; i += 256)  sW2[i] = W2[i];
    float prelu = pa[0];
    int m0 = blockIdx.x * 64;
    for (int i = t; i < 64 * 128; i += 256) {
        int r = i >> 7, k = i & 127;
        int node = m0 + r;
        sh[r * 129 + k] = (node < N_NODES) ? g_h[node * 128 + k] : 0.f;
    }
    __syncthreads();
    int tx = t & 15, ty = t >> 4;
    int c0 = tx * 8, r0 = ty * 4;
    float acc[4][8];
#pragma unroll
    for (int r = 0; r < 4; r++)
#pragma unroll
        for (int j = 0; j < 8; j++) acc[r][j] = 0.f;

    for (int k = 0; k < 128; k++) {
        const float4* wrow = (const float4*)&sW1[k * 128 + c0];
        float4 wa = wrow[0], wb = wrow[1];
        float w[8] = { wa.x, wa.y, wa.z, wa.w, wb.x, wb.y, wb.z, wb.w };
#pragma unroll
        for (int r = 0; r < 4; r++) {
            float hv = sh[(r0 + r) * 129 + k];
#pragma unroll
            for (int j = 0; j < 8; j++) acc[r][j] = fmaf(hv, w[j], acc[r][j]);
        }
    }
    __syncthreads();
    // b1 + PReLU, write h1 back into sh
#pragma unroll
    for (int r = 0; r < 4; r++) {
#pragma unroll
        for (int j = 0; j < 8; j++) {
            float v = acc[r][j] + b1[c0 + j];
            v = v > 0.f ? v : prelu * v;
            sh[(r0 + r) * 129 + c0 + j] = v;
        }
    }
    __syncthreads();
    // layer 2: each thread: one row (4 threads/row), 8 cols
    int rr = t >> 2, cb = (t & 3) * 8;
    float a2[8];
#pragma unroll
    for (int j = 0; j < 8; j++) a2[j] = 0.f;
    for (int k = 0; k < 128; k++) {
        float hv = sh[rr * 129 + k];
        const float4* wrow = (const float4*)&sW2[k * 32 + cb];
        float4 wa = wrow[0], wb = wrow[1];
        a2[0] = fmaf(hv, wa.x, a2[0]); a2[1] = fmaf(hv, wa.y, a2[1]);
        a2[2] = fmaf(hv, wa.z, a2[2]); a2[3] = fmaf(hv, wa.w, a2[3]);
        a2[4] = fmaf(hv, wb.x, a2[4]); a2[5] = fmaf(hv, wb.y, a2[5]);
        a2[6] = fmaf(hv, wb.z, a2[6]); a2[7] = fmaf(hv, wb.w, a2[7]);
    }
    int node = m0 + rr;
    if (node < N_NODES) {
#pragma unroll
        for (int j = 0; j < 8; j++) out[node * 32 + cb + j] = a2[j] + b2[cb + j];
    }
}

// ---------------- launch ----------------
extern "C" void kernel_launch(void* const* d_in, const int* in_sizes, int n_in,
                              void* d_out, int out_size) {
    const float*     x        = (const float*)d_in[0];
    const void*      ei       = d_in[1];
    const float*     ea       = (const float*)d_in[2];
    const float*     W_gat    = (const float*)d_in[3];
    const float*     att_src  = (const float*)d_in[4];
    const float*     att_dst  = (const float*)d_in[5];
    const float*     W_edge   = (const float*)d_in[6];
    const float*     att_edge = (const float*)d_in[7];
    const float*     bias_gat = (const float*)d_in[8];
    const float*     W1       = (const float*)d_in[9];
    const float*     b1       = (const float*)d_in[10];
    const float*     prelu_a  = (const float*)d_in[11];
    const float*     W2       = (const float*)d_in[12];
    const float*     b2       = (const float*)d_in[13];
    float*           out      = (float*)d_out;

    cudaFuncSetAttribute(k_mlp, cudaFuncAttributeMaxDynamicSharedMemorySize, MLP_SMEM);

    k_detect<<<1, 64>>>((const int*)ei);
    k_zero<<<(7 * N_NODES + 255) / 256, 256>>>();
    k_deg<<<(NE + 255) / 256, 256>>>(ei, ea);
    k_foldM<<<1, 32>>>(W_edge, att_edge);
    k_node<<<(N_NODES * 32 + 255) / 256, 256>>>(x, W_gat, att_src, att_dst);
    k_scan<<<1, 1024>>>();
    k_edge<<<(NT + 255) / 256, 256>>>(ei, ea);
    k_agg<<<(N_NODES * 32 + 255) / 256, 256>>>(bias_gat);
    k_mlp<<<(N_NODES + 63) / 64, 256, MLP_SMEM>>>(W1, b1, prelu_a, W2, b2, out);
}

// round 5
// speedup vs baseline: 1.1934x; 1.1934x over previous
#include <cuda_runtime.h>
#include <cuda_bf16.h>
#include <math.h>
#include <mma.h>

namespace wm = nvcuda::wmma;

#define N_NODES 50000
#define NE      1600000
#define NT      (NE + N_NODES)     // edges + self loops
#define HH      4
#define CC      32
#define FF      128                // HH*CC
#define NEG_SLOPE 0.2f

// ---------------- scratch (device globals; no allocations allowed) ----------------
__device__ __align__(16) float  g_xp[N_NODES * FF];     // projected features  [N,128]
__device__ __align__(16) float  g_asrc[N_NODES * 4];
__device__ __align__(16) float  g_adst[N_NODES * 4];
__device__ __align__(16) float  g_aesum[N_NODES * 4];   // folded edge-att segment sum (per head)
__device__ __align__(16) int    g_deg[N_NODES];
__device__ __align__(16) int    g_rowptr[N_NODES + 4];
__device__ __align__(16) int    g_wptr[N_NODES + 4];
__device__ int    g_csrc[NT];
__device__ float4 g_calpha[NT];
__device__ __align__(16) float  g_aloop[N_NODES * 4];
__device__ __align__(16) float  g_h[N_NODES * FF];      // ELU(out+bias) hidden
__device__ float  g_M[7 * 4];                           // folded edge attention matrix
__device__ int    g_is64;                               // edge_index dtype flag

__device__ __forceinline__ float lrelu(float v) { return v > 0.f ? v : NEG_SLOPE * v; }

// index accessor that works for both int32 and int64 edge_index
__device__ __forceinline__ int ld_idx(const void* ei, int pos) {
    if (g_is64) return (int)((const long long*)ei)[pos];
    return ((const int*)ei)[pos];
}

// ---------------- K0: zero counters + dtype detect + fold M (merged) ----------------
__global__ void k_init(const int* __restrict__ ei_w, const float* __restrict__ W_edge,
                       const float* __restrict__ att_edge) {
    int t = blockIdx.x * blockDim.x + threadIdx.x;
    if (t < N_NODES) {
        g_deg[t] = 0;
        *(float4*)&g_aesum[t * 4] = make_float4(0.f, 0.f, 0.f, 0.f);
    }
    if (blockIdx.x == 0) {
        __shared__ int ok[2];
        int tt = threadIdx.x;
        if (tt < 64) {
            // int64 little-endian values < 2^31 have zero high words at odd 32-bit offsets
            int v = ei_w[2 * tt + 1];
            unsigned ball = __ballot_sync(0xFFFFFFFFu, v == 0);
            if ((tt & 31) == 0) ok[tt >> 5] = (ball == 0xFFFFFFFFu) ? 1 : 0;
        }
        __syncthreads();
        if (tt == 0) g_is64 = ok[0] & ok[1];
        if (tt < 28) {
            int k = tt >> 2, h = tt & 3;
            float s = 0.f;
            for (int c = 0; c < CC; c++) s += W_edge[k * FF + h * CC + c] * att_edge[h * CC + c];
            g_M[k * 4 + h] = s;
        }
    }
}

// ---------------- K1: in-degree + folded edge-attention segment sum ----------------
__global__ void k_deg(const void* __restrict__ ei, const float* __restrict__ ea) {
    int e = blockIdx.x * blockDim.x + threadIdx.x;
    if (e >= NE) return;
    int dst = ld_idx(ei, NE + e);
    atomicAdd(&g_deg[dst], 1);
    float ev[7];
#pragma unroll
    for (int k = 0; k < 7; k++) ev[k] = ea[e * 7 + k];
#pragma unroll
    for (int h = 0; h < 4; h++) {
        float s = 0.f;
#pragma unroll
        for (int k = 0; k < 7; k++) s = fmaf(ev[k], g_M[k * 4 + h], s);
        atomicAdd(&g_aesum[dst * 4 + h], s);
    }
}

// ---------------- K3: per-node projection, a_src/a_dst, self-loop alpha ----------------
__global__ void k_node(const float* __restrict__ x, const float* __restrict__ W_gat,
                       const float* __restrict__ att_src, const float* __restrict__ att_dst) {
    int warp = (blockIdx.x * blockDim.x + threadIdx.x) >> 5;
    int lane = threadIdx.x & 31;
    if (warp >= N_NODES) return;
    int n = warp;
    float x0 = x[n * 3 + 0], x1 = x[n * 3 + 1], x2 = x[n * 3 + 2];
    int i0 = lane * 4;
    float v[4];
    float as = 0.f, ad = 0.f;
#pragma unroll
    for (int j = 0; j < 4; j++) {
        int i = i0 + j;
        float p = fmaf(x0, W_gat[i], fmaf(x1, W_gat[FF + i], x2 * W_gat[2 * FF + i]));
        v[j] = p;
        as = fmaf(p, att_src[i], as);
        ad = fmaf(p, att_dst[i], ad);
    }
    *(float4*)&g_xp[n * FF + i0] = make_float4(v[0], v[1], v[2], v[3]);
    // reduce within each 8-lane group (one group per head)
#pragma unroll
    for (int o = 1; o < 8; o <<= 1) {
        as += __shfl_xor_sync(0xFFFFFFFFu, as, o);
        ad += __shfl_xor_sync(0xFFFFFFFFu, ad, o);
    }
    int h = lane >> 3;
    if ((lane & 7) == 0) {
        g_asrc[n * 4 + h] = as;
        g_adst[n * 4 + h] = ad;
    }
    // self loop alpha (pre-softmax), lanes 0..3 compute head=lane
    float asum_h = __shfl_sync(0xFFFFFFFFu, as + ad, (lane & 3) * 8);
    if (lane < 4) {
        int hh = lane;
        float invd = 1.0f / fmaxf((float)g_deg[n], 1.0f);
        float ae = g_aesum[n * 4 + hh] * invd;
        g_aloop[n * 4 + hh] = lrelu(asum_h + ae);
    }
}

// ---------------- K4: exclusive scan of (deg+1) -> row_ptr, wptr (x4 vectorized) ----------------
__global__ void k_scan() {
    __shared__ int wsum[32];
    __shared__ int s_carry;
    int t = threadIdx.x, lane = t & 31, w = t >> 5;
    if (t == 0) s_carry = 0;
    __syncthreads();
    const int CHUNK = 4096;   // 1024 threads * 4
    for (int base = 0; base < N_NODES; base += CHUNK) {
        int i0 = base + t * 4;
        int v0 = 0, v1 = 0, v2 = 0, v3 = 0;
        if (i0 < N_NODES) {   // N_NODES % 4 == 0, so full int4 is in-bounds
            int4 d = *(const int4*)&g_deg[i0];
            v0 = d.x + 1; v1 = d.y + 1; v2 = d.z + 1; v3 = d.w + 1;
        }
        int tsum = v0 + v1 + v2 + v3;
        int s = tsum;
#pragma unroll
        for (int o = 1; o < 32; o <<= 1) {
            int u = __shfl_up_sync(0xFFFFFFFFu, s, o);
            if (lane >= o) s += u;
        }
        if (lane == 31) wsum[w] = s;
        __syncthreads();
        if (w == 0) {
            int ws = wsum[lane];
#pragma unroll
            for (int o = 1; o < 32; o <<= 1) {
                int u = __shfl_up_sync(0xFFFFFFFFu, ws, o);
                if (lane >= o) ws += u;
            }
            wsum[lane] = ws;
        }
        __syncthreads();
        int excl = s_carry + (w > 0 ? wsum[w - 1] : 0) + s - tsum;
        if (i0 < N_NODES) {
            int4 r;
            r.x = excl; r.y = excl + v0; r.z = excl + v0 + v1; r.w = excl + v0 + v1 + v2;
            *(int4*)&g_rowptr[i0] = r;
            *(int4*)&g_wptr[i0] = r;
        }
        int total = wsum[31];
        __syncthreads();
        if (t == 0) s_carry += total;
        __syncthreads();
    }
    if (t == 0) g_rowptr[N_NODES] = s_carry;
}

// ---------------- K5: per-edge alpha + CSR scatter (incl. self loops) ----------------
__global__ void k_edge(const void* __restrict__ ei, const float* __restrict__ ea) {
    int t = blockIdx.x * blockDim.x + threadIdx.x;
    if (t >= NT) return;
    int src, dst;
    float4 a4;
    if (t < NE) {
        src = ld_idx(ei, t);
        dst = ld_idx(ei, NE + t);
        float e[7];
#pragma unroll
        for (int k = 0; k < 7; k++) e[k] = ea[t * 7 + k];
        float ah[4];
#pragma unroll
        for (int h = 0; h < 4; h++) {
            float s = 0.f;
#pragma unroll
            for (int k = 0; k < 7; k++) s = fmaf(e[k], g_M[k * 4 + h], s);
            ah[h] = s;
        }
        float4 as = *(const float4*)&g_asrc[src * 4];
        float4 ad = *(const float4*)&g_adst[dst * 4];
        a4.x = lrelu(as.x + ad.x + ah[0]);
        a4.y = lrelu(as.y + ad.y + ah[1]);
        a4.z = lrelu(as.z + ad.z + ah[2]);
        a4.w = lrelu(as.w + ad.w + ah[3]);
    } else {
        int n = t - NE;
        src = n; dst = n;
        a4 = *(const float4*)&g_aloop[n * 4];
    }
    int pos = atomicAdd(&g_wptr[dst], 1);
    g_csrc[pos] = src;
    g_calpha[pos] = a4;
}

// ---------------- K6: per-node softmax + weighted aggregation (warp/node) ----------------
__global__ void k_agg(const float* __restrict__ bias) {
    int warp = (blockIdx.x * blockDim.x + threadIdx.x) >> 5;
    int lane = threadIdx.x & 31;
    if (warp >= N_NODES) return;
    int n = warp;
    int rs = g_rowptr[n], re = g_rowptr[n + 1];

    // pass A: component-wise max (per head)
    float4 m4 = make_float4(-1e30f, -1e30f, -1e30f, -1e30f);
    for (int i = rs + lane; i < re; i += 32) {
        float4 a = g_calpha[i];
        m4.x = fmaxf(m4.x, a.x); m4.y = fmaxf(m4.y, a.y);
        m4.z = fmaxf(m4.z, a.z); m4.w = fmaxf(m4.w, a.w);
    }
#pragma unroll
    for (int o = 16; o > 0; o >>= 1) {
        m4.x = fmaxf(m4.x, __shfl_xor_sync(0xFFFFFFFFu, m4.x, o));
        m4.y = fmaxf(m4.y, __shfl_xor_sync(0xFFFFFFFFu, m4.y, o));
        m4.z = fmaxf(m4.z, __shfl_xor_sync(0xFFFFFFFFu, m4.z, o));
        m4.w = fmaxf(m4.w, __shfl_xor_sync(0xFFFFFFFFu, m4.w, o));
    }
    // pass B: exp-sum
    float4 d4 = make_float4(0.f, 0.f, 0.f, 0.f);
    for (int i = rs + lane; i < re; i += 32) {
        float4 a = g_calpha[i];
        d4.x += __expf(a.x - m4.x); d4.y += __expf(a.y - m4.y);
        d4.z += __expf(a.z - m4.z); d4.w += __expf(a.w - m4.w);
    }
#pragma unroll
    for (int o = 16; o > 0; o >>= 1) {
        d4.x += __shfl_xor_sync(0xFFFFFFFFu, d4.x, o);
        d4.y += __shfl_xor_sync(0xFFFFFFFFu, d4.y, o);
        d4.z += __shfl_xor_sync(0xFFFFFFFFu, d4.z, o);
        d4.w += __shfl_xor_sync(0xFFFFFFFFu, d4.w, o);
    }
    int h = lane >> 3;
    float mh  = (h == 0) ? m4.x : (h == 1) ? m4.y : (h == 2) ? m4.z : m4.w;
    float dh  = (h == 0) ? d4.x : (h == 1) ? d4.y : (h == 2) ? d4.z : d4.w;
    float ih  = 1.0f / dh;

    const float* abase = (const float*)g_calpha;
    float4 acc = make_float4(0.f, 0.f, 0.f, 0.f);
    int i = rs;
    for (; i + 4 <= re; i += 4) {
        int s0 = g_csrc[i + 0], s1 = g_csrc[i + 1], s2 = g_csrc[i + 2], s3 = g_csrc[i + 3];
        float w0 = __expf(abase[(i + 0) * 4 + h] - mh) * ih;
        float w1 = __expf(abase[(i + 1) * 4 + h] - mh) * ih;
        float w2 = __expf(abase[(i + 2) * 4 + h] - mh) * ih;
        float w3 = __expf(abase[(i + 3) * 4 + h] - mh) * ih;
        float4 v0 = *(const float4*)&g_xp[s0 * FF + lane * 4];
        float4 v1 = *(const float4*)&g_xp[s1 * FF + lane * 4];
        float4 v2 = *(const float4*)&g_xp[s2 * FF + lane * 4];
        float4 v3 = *(const float4*)&g_xp[s3 * FF + lane * 4];
        acc.x += w0 * v0.x + w1 * v1.x + w2 * v2.x + w3 * v3.x;
        acc.y += w0 * v0.y + w1 * v1.y + w2 * v2.y + w3 * v3.y;
        acc.z += w0 * v0.z + w1 * v1.z + w2 * v2.z + w3 * v3.z;
        acc.w += w0 * v0.w + w1 * v1.w + w2 * v2.w + w3 * v3.w;
    }
    for (; i < re; i++) {
        int s0 = g_csrc[i];
        float w0 = __expf(abase[i * 4 + h] - mh) * ih;
        float4 v0 = *(const float4*)&g_xp[s0 * FF + lane * 4];
        acc.x += w0 * v0.x; acc.y += w0 * v0.y;
        acc.z += w0 * v0.z; acc.w += w0 * v0.w;
    }
    // ELU(out + bias)
    float4 b = *(const float4*)&bias[lane * 4];
    float r0 = acc.x + b.x, r1 = acc.y + b.y, r2 = acc.z + b.z, r3 = acc.w + b.w;
    r0 = r0 > 0.f ? r0 : expm1f(r0);
    r1 = r1 > 0.f ? r1 : expm1f(r1);
    r2 = r2 > 0.f ? r2 : expm1f(r2);
    r3 = r3 > 0.f ? r3 : expm1f(r3);
    *(float4*)&g_h[n * FF + lane * 4] = make_float4(r0, r1, r2, r3);
}

// ---------------- K7: fused MLP via tf32 tensor cores ----------------
// smem: sW1[128][128] + sW2[128][32] + shA[64][132] + sh1[64][132]
#define MLP_SMEM (16384*4 + 4096*4 + 8448*4 + 8448*4)
__global__ void k_mlp(const float* __restrict__ W1, const float* __restrict__ b1,
                      const float* __restrict__ pa, const float* __restrict__ W2,
                      const float* __restrict__ b2, float* __restrict__ out) {
    extern __shared__ float smem[];
    float* sW1 = smem;              // [128][128]
    float* sW2 = sW1 + 16384;       // [128][32]
    float* shA = sW2 + 4096;        // [64][132]  input h (then layer-2 output)
    float* sh1 = shA + 8448;        // [64][132]  hidden h1
    int t = threadIdx.x;
    int w = t >> 5;
    int m0 = blockIdx.x * 64;

    for (int i = t; i < 16384; i += 256) sW1[i] = W1[i];
    for (int i = t; i < 4096; i += 256)  sW2[i] = W2[i];
    for (int i = t; i < 64 * 128; i += 256) {
        int r = i >> 7, k = i & 127;
        int node = m0 + r;
        shA[r * 132 + k] = (node < N_NODES) ? g_h[node * 128 + k] : 0.f;
    }
    float prelu = pa[0];
    __syncthreads();

    // ---- layer 1: [64x128] @ [128x128]; 8 warps, each a 32x32 tile ----
    {
        int wr = w >> 2, wc = w & 3;
        wm::fragment<wm::accumulator, 16, 16, 8, float> acc[2][2];
#pragma unroll
        for (int i = 0; i < 2; i++)
#pragma unroll
            for (int j = 0; j < 2; j++) wm::fill_fragment(acc[i][j], 0.f);
        for (int k = 0; k < 128; k += 8) {
            wm::fragment<wm::matrix_a, 16, 16, 8, wm::precision::tf32, wm::row_major> a[2];
            wm::fragment<wm::matrix_b, 16, 16, 8, wm::precision::tf32, wm::row_major> b[2];
#pragma unroll
            for (int i = 0; i < 2; i++) {
                wm::load_matrix_sync(a[i], &shA[(wr * 32 + i * 16) * 132 + k], 132);
#pragma unroll
                for (int e = 0; e < a[i].num_elements; e++) a[i].x[e] = wm::__float_to_tf32(a[i].x[e]);
            }
#pragma unroll
            for (int j = 0; j < 2; j++) {
                wm::load_matrix_sync(b[j], &sW1[k * 128 + wc * 32 + j * 16], 128);
#pragma unroll
                for (int e = 0; e < b[j].num_elements; e++) b[j].x[e] = wm::__float_to_tf32(b[j].x[e]);
            }
#pragma unroll
            for (int i = 0; i < 2; i++)
#pragma unroll
                for (int j = 0; j < 2; j++)
                    wm::mma_sync(acc[i][j], a[i], b[j], acc[i][j]);
        }
#pragma unroll
        for (int i = 0; i < 2; i++)
#pragma unroll
            for (int j = 0; j < 2; j++)
                wm::store_matrix_sync(&sh1[(wr * 32 + i * 16) * 132 + wc * 32 + j * 16],
                                      acc[i][j], 132, wm::mem_row_major);
    }
    __syncthreads();
    // bias + PReLU in place
    for (int i = t; i < 64 * 128; i += 256) {
        int r = i >> 7, c = i & 127;
        float v = sh1[r * 132 + c] + b1[c];
        sh1[r * 132 + c] = v > 0.f ? v : prelu * v;
    }
    __syncthreads();
    // ---- layer 2: [64x128] @ [128x32]; 8 warps, each one 16x16 tile ----
    {
        int wr = w >> 1, wc = w & 1;
        wm::fragment<wm::accumulator, 16, 16, 8, float> acc;
        wm::fill_fragment(acc, 0.f);
        for (int k = 0; k < 128; k += 8) {
            wm::fragment<wm::matrix_a, 16, 16, 8, wm::precision::tf32, wm::row_major> a;
            wm::fragment<wm::matrix_b, 16, 16, 8, wm::precision::tf32, wm::row_major> b;
            wm::load_matrix_sync(a, &sh1[(wr * 16) * 132 + k], 132);
#pragma unroll
            for (int e = 0; e < a.num_elements; e++) a.x[e] = wm::__float_to_tf32(a.x[e]);
            wm::load_matrix_sync(b, &sW2[k * 32 + wc * 16], 32);
#pragma unroll
            for (int e = 0; e < b.num_elements; e++) b.x[e] = wm::__float_to_tf32(b.x[e]);
            wm::mma_sync(acc, a, b, acc);
        }
        wm::store_matrix_sync(&shA[(wr * 16) * 132 + wc * 16], acc, 132, wm::mem_row_major);
    }
    __syncthreads();
    // write out with b2
    for (int i = t; i < 64 * 32; i += 256) {
        int r = i >> 5, c = i & 31;
        int node = m0 + r;
        if (node < N_NODES) out[node * 32 + c] = shA[r * 132 + c] + b2[c];
    }
}

// ---------------- launch ----------------
extern "C" void kernel_launch(void* const* d_in, const int* in_sizes, int n_in,
                              void* d_out, int out_size) {
    const float*     x        = (const float*)d_in[0];
    const void*      ei       = d_in[1];
    const float*     ea       = (const float*)d_in[2];
    const float*     W_gat    = (const float*)d_in[3];
    const float*     att_src  = (const float*)d_in[4];
    const float*     att_dst  = (const float*)d_in[5];
    const float*     W_edge   = (const float*)d_in[6];
    const float*     att_edge = (const float*)d_in[7];
    const float*     bias_gat = (const float*)d_in[8];
    const float*     W1       = (const float*)d_in[9];
    const float*     b1       = (const float*)d_in[10];
    const float*     prelu_a  = (const float*)d_in[11];
    const float*     W2       = (const float*)d_in[12];
    const float*     b2       = (const float*)d_in[13];
    float*           out      = (float*)d_out;

    cudaFuncSetAttribute(k_mlp, cudaFuncAttributeMaxDynamicSharedMemorySize, MLP_SMEM);

    k_init<<<(N_NODES + 255) / 256, 256>>>((const int*)ei, W_edge, att_edge);
    k_deg<<<(NE + 255) / 256, 256>>>(ei, ea);
    k_node<<<(N_NODES * 32 + 255) / 256, 256>>>(x, W_gat, att_src, att_dst);
    k_scan<<<1, 1024>>>();
    k_edge<<<(NT + 255) / 256, 256>>>(ei, ea);
    k_agg<<<(N_NODES * 32 + 255) / 256, 256>>>(bias_gat);
    k_mlp<<<(N_NODES + 63) / 64, 256, MLP_SMEM>>>(W1, b1, prelu_a, W2, b2, out);
}

// round 6
// speedup vs baseline: 1.2951x; 1.0852x over previous
#include <cuda_runtime.h>
#include <cuda_bf16.h>
#include <math.h>
#include <mma.h>

namespace wm = nvcuda::wmma;

#define N_NODES 50000
#define NE      1600000
#define HH      4
#define CC      32
#define FF      128                // HH*CC
#define NEG_SLOPE 0.2f
#define SCAN_BLOCKS 13             // ceil(50000 / 4096)

// ---------------- scratch (device globals; no allocations allowed) ----------------
__device__ __align__(16) float  g_xp[N_NODES * FF];     // projected features  [N,128]
__device__ __align__(16) float  g_asrc[N_NODES * 4];
__device__ __align__(16) float  g_adst[N_NODES * 4];
__device__ __align__(16) float  g_aesum[N_NODES * 4];   // folded edge-att segment sum (per head)
__device__ __align__(16) int    g_deg[N_NODES];
__device__ __align__(16) int    g_rowptr[N_NODES + 4];
__device__ __align__(16) int    g_wptr[N_NODES + 4];
__device__ int    g_csrc[NE];
__device__ float4 g_calpha[NE];
__device__ __align__(16) float  g_h[N_NODES * FF];      // ELU(out+bias) hidden
__device__ float  g_M[7 * 4];                           // folded edge attention matrix
__device__ int    g_is64;                               // edge_index dtype flag
__device__ unsigned g_scanstate[SCAN_BLOCKS];

__device__ __forceinline__ float lrelu(float v) { return v > 0.f ? v : NEG_SLOPE * v; }

// index accessor that works for both int32 and int64 edge_index
__device__ __forceinline__ int ld_idx(const void* ei, int pos) {
    if (g_is64) return (int)((const long long*)ei)[pos];
    return ((const int*)ei)[pos];
}

__device__ __forceinline__ void red_add_v4(float* p, float4 v) {
    asm volatile("red.global.add.v4.f32 [%0], {%1,%2,%3,%4};"
                 :: "l"(p), "f"(v.x), "f"(v.y), "f"(v.z), "f"(v.w) : "memory");
}

// ---------------- K0: zero counters + dtype detect + fold M (merged) ----------------
__global__ void k_init(const int* __restrict__ ei_w, const float* __restrict__ W_edge,
                       const float* __restrict__ att_edge) {
    int t = blockIdx.x * blockDim.x + threadIdx.x;
    if (t < N_NODES) {
        g_deg[t] = 0;
        *(float4*)&g_aesum[t * 4] = make_float4(0.f, 0.f, 0.f, 0.f);
    }
    if (blockIdx.x == 0) {
        __shared__ int ok[2];
        int tt = threadIdx.x;
        if (tt < SCAN_BLOCKS) g_scanstate[tt] = 0u;
        if (tt < 64) {
            // int64 little-endian values < 2^31 have zero high words at odd 32-bit offsets
            int v = ei_w[2 * tt + 1];
            unsigned ball = __ballot_sync(0xFFFFFFFFu, v == 0);
            if ((tt & 31) == 0) ok[tt >> 5] = (ball == 0xFFFFFFFFu) ? 1 : 0;
        }
        __syncthreads();
        if (tt == 0) g_is64 = ok[0] & ok[1];
        if (tt < 28) {
            int k = tt >> 2, h = tt & 3;
            float s = 0.f;
            for (int c = 0; c < CC; c++) s += W_edge[k * FF + h * CC + c] * att_edge[h * CC + c];
            g_M[k * 4 + h] = s;
        }
    }
}

// ---------------- K1: in-degree + folded edge-attention segment sum ----------------
__global__ void k_deg(const void* __restrict__ ei, const float* __restrict__ ea) {
    int e = blockIdx.x * blockDim.x + threadIdx.x;
    if (e >= NE) return;
    int dst = ld_idx(ei, NE + e);
    atomicAdd(&g_deg[dst], 1);
    float ev[7];
#pragma unroll
    for (int k = 0; k < 7; k++) ev[k] = ea[e * 7 + k];
    float4 s4;
    float* s = (float*)&s4;
#pragma unroll
    for (int h = 0; h < 4; h++) {
        float s0 = 0.f;
#pragma unroll
        for (int k = 0; k < 7; k++) s0 = fmaf(ev[k], g_M[k * 4 + h], s0);
        s[h] = s0;
    }
    red_add_v4(&g_aesum[dst * 4], s4);
}

// ---------------- K2: per-node projection + a_src/a_dst ----------------
__global__ void k_node(const float* __restrict__ x, const float* __restrict__ W_gat,
                       const float* __restrict__ att_src, const float* __restrict__ att_dst) {
    int warp = (blockIdx.x * blockDim.x + threadIdx.x) >> 5;
    int lane = threadIdx.x & 31;
    if (warp >= N_NODES) return;
    int n = warp;
    float x0 = x[n * 3 + 0], x1 = x[n * 3 + 1], x2 = x[n * 3 + 2];
    int i0 = lane * 4;
    float v[4];
    float as = 0.f, ad = 0.f;
#pragma unroll
    for (int j = 0; j < 4; j++) {
        int i = i0 + j;
        float p = fmaf(x0, W_gat[i], fmaf(x1, W_gat[FF + i], x2 * W_gat[2 * FF + i]));
        v[j] = p;
        as = fmaf(p, att_src[i], as);
        ad = fmaf(p, att_dst[i], ad);
    }
    *(float4*)&g_xp[n * FF + i0] = make_float4(v[0], v[1], v[2], v[3]);
    // reduce within each 8-lane group (one group per head)
#pragma unroll
    for (int o = 1; o < 8; o <<= 1) {
        as += __shfl_xor_sync(0xFFFFFFFFu, as, o);
        ad += __shfl_xor_sync(0xFFFFFFFFu, ad, o);
    }
    int h = lane >> 3;
    if ((lane & 7) == 0) {
        g_asrc[n * 4 + h] = as;
        g_adst[n * 4 + h] = ad;
    }
}

// ---------------- K3: single-pass decoupled-lookback exclusive scan of deg ----------------
__global__ void k_scan() {
    __shared__ int wsum[32];
    __shared__ int s_prefix;
    int bid = blockIdx.x;
    int t = threadIdx.x, lane = t & 31, w = t >> 5;
    int i0 = bid * 4096 + t * 4;
    int v0 = 0, v1 = 0, v2 = 0, v3 = 0;
    if (i0 < N_NODES) {   // N_NODES % 4 == 0 -> full int4 in-bounds
        int4 d = *(const int4*)&g_deg[i0];
        v0 = d.x; v1 = d.y; v2 = d.z; v3 = d.w;
    }
    int tsum = v0 + v1 + v2 + v3;
    int s = tsum;
#pragma unroll
    for (int o = 1; o < 32; o <<= 1) {
        int u = __shfl_up_sync(0xFFFFFFFFu, s, o);
        if (lane >= o) s += u;
    }
    if (lane == 31) wsum[w] = s;
    __syncthreads();
    if (w == 0) {
        int ws = wsum[lane];
#pragma unroll
        for (int o = 1; o < 32; o <<= 1) {
            int u = __shfl_up_sync(0xFFFFFFFFu, ws, o);
            if (lane >= o) ws += u;
        }
        wsum[lane] = ws;
    }
    __syncthreads();
    int excl = (w > 0 ? wsum[w - 1] : 0) + s - tsum;
    int agg = wsum[31];
    if (t == 0) {
        // publish aggregate (or inclusive for block 0)
        unsigned pub = (bid == 0) ? (0x80000000u | (unsigned)agg) : (0x40000000u | (unsigned)agg);
        atomicExch(&g_scanstate[bid], pub);
        int prefix = 0;
        if (bid > 0) {
            for (int j = bid - 1; j >= 0; ) {
                unsigned st;
                do { st = atomicAdd(&g_scanstate[j], 0u); } while (st == 0u);
                prefix += (int)(st & 0x3FFFFFFFu);
                if (st & 0x80000000u) break;
                j--;
            }
            atomicExch(&g_scanstate[bid], 0x80000000u | (unsigned)(prefix + agg));
        }
        s_prefix = prefix;
        if (bid == SCAN_BLOCKS - 1) g_rowptr[N_NODES] = prefix + agg;
    }
    __syncthreads();
    int base = s_prefix + excl;
    if (i0 < N_NODES) {
        int4 r;
        r.x = base; r.y = base + v0; r.z = base + v0 + v1; r.w = base + v0 + v1 + v2;
        *(int4*)&g_rowptr[i0] = r;
        *(int4*)&g_wptr[i0] = r;
    }
}

// ---------------- K4: per-edge alpha + CSR scatter (real edges only) ----------------
__global__ void k_edge(const void* __restrict__ ei, const float* __restrict__ ea) {
    int t = blockIdx.x * blockDim.x + threadIdx.x;
    if (t >= NE) return;
    int src = ld_idx(ei, t);
    int dst = ld_idx(ei, NE + t);
    float e[7];
#pragma unroll
    for (int k = 0; k < 7; k++) e[k] = ea[t * 7 + k];
    float ah[4];
#pragma unroll
    for (int h = 0; h < 4; h++) {
        float s = 0.f;
#pragma unroll
        for (int k = 0; k < 7; k++) s = fmaf(e[k], g_M[k * 4 + h], s);
        ah[h] = s;
    }
    float4 as = *(const float4*)&g_asrc[src * 4];
    float4 ad = *(const float4*)&g_adst[dst * 4];
    float4 a4;
    a4.x = lrelu(as.x + ad.x + ah[0]);
    a4.y = lrelu(as.y + ad.y + ah[1]);
    a4.z = lrelu(as.z + ad.z + ah[2]);
    a4.w = lrelu(as.w + ad.w + ah[3]);
    int pos = atomicAdd(&g_wptr[dst], 1);
    g_csrc[pos] = src;
    g_calpha[pos] = a4;
}

// ---------------- K5: per-node softmax + aggregation; self-loop computed inline ----------------
__global__ void k_agg(const float* __restrict__ bias) {
    int warp = (blockIdx.x * blockDim.x + threadIdx.x) >> 5;
    int lane = threadIdx.x & 31;
    if (warp >= N_NODES) return;
    int n = warp;
    int rs = g_rowptr[n], re = g_rowptr[n + 1];
    int deg = re - rs;

    // self-loop alpha (same in every lane)
    float4 as4 = *(const float4*)&g_asrc[n * 4];
    float4 ad4 = *(const float4*)&g_adst[n * 4];
    float4 ae4 = *(const float4*)&g_aesum[n * 4];
    float invd = 1.0f / fmaxf((float)deg, 1.0f);
    float4 asl;
    asl.x = lrelu(as4.x + ad4.x + ae4.x * invd);
    asl.y = lrelu(as4.y + ad4.y + ae4.y * invd);
    asl.z = lrelu(as4.z + ad4.z + ae4.z * invd);
    asl.w = lrelu(as4.w + ad4.w + ae4.w * invd);

    // pass A: component-wise max (per head); seed with self-loop
    float4 m4 = asl;
    for (int i = rs + lane; i < re; i += 32) {
        float4 a = g_calpha[i];
        m4.x = fmaxf(m4.x, a.x); m4.y = fmaxf(m4.y, a.y);
        m4.z = fmaxf(m4.z, a.z); m4.w = fmaxf(m4.w, a.w);
    }
#pragma unroll
    for (int o = 16; o > 0; o >>= 1) {
        m4.x = fmaxf(m4.x, __shfl_xor_sync(0xFFFFFFFFu, m4.x, o));
        m4.y = fmaxf(m4.y, __shfl_xor_sync(0xFFFFFFFFu, m4.y, o));
        m4.z = fmaxf(m4.z, __shfl_xor_sync(0xFFFFFFFFu, m4.z, o));
        m4.w = fmaxf(m4.w, __shfl_xor_sync(0xFFFFFFFFu, m4.w, o));
    }
    // pass B: exp-sum over edges
    float4 d4 = make_float4(0.f, 0.f, 0.f, 0.f);
    for (int i = rs + lane; i < re; i += 32) {
        float4 a = g_calpha[i];
        d4.x += __expf(a.x - m4.x); d4.y += __expf(a.y - m4.y);
        d4.z += __expf(a.z - m4.z); d4.w += __expf(a.w - m4.w);
    }
#pragma unroll
    for (int o = 16; o > 0; o >>= 1) {
        d4.x += __shfl_xor_sync(0xFFFFFFFFu, d4.x, o);
        d4.y += __shfl_xor_sync(0xFFFFFFFFu, d4.y, o);
        d4.z += __shfl_xor_sync(0xFFFFFFFFu, d4.z, o);
        d4.w += __shfl_xor_sync(0xFFFFFFFFu, d4.w, o);
    }
    int h = lane >> 3;
    float mh   = (h == 0) ? m4.x : (h == 1) ? m4.y : (h == 2) ? m4.z : m4.w;
    float aslh = (h == 0) ? asl.x : (h == 1) ? asl.y : (h == 2) ? asl.z : asl.w;
    float dh   = (h == 0) ? d4.x : (h == 1) ? d4.y : (h == 2) ? d4.z : d4.w;
    float wsl  = __expf(aslh - mh);           // self-loop exp term
    dh += wsl;
    float ih = 1.0f / dh;

    const float* abase = (const float*)g_calpha;
    float4 acc = make_float4(0.f, 0.f, 0.f, 0.f);
    int i = rs;
    for (; i + 4 <= re; i += 4) {
        int s0 = g_csrc[i + 0], s1 = g_csrc[i + 1], s2 = g_csrc[i + 2], s3 = g_csrc[i + 3];
        float w0 = __expf(abase[(i + 0) * 4 + h] - mh) * ih;
        float w1 = __expf(abase[(i + 1) * 4 + h] - mh) * ih;
        float w2 = __expf(abase[(i + 2) * 4 + h] - mh) * ih;
        float w3 = __expf(abase[(i + 3) * 4 + h] - mh) * ih;
        float4 v0 = *(const float4*)&g_xp[s0 * FF + lane * 4];
        float4 v1 = *(const float4*)&g_xp[s1 * FF + lane * 4];
        float4 v2 = *(const float4*)&g_xp[s2 * FF + lane * 4];
        float4 v3 = *(const float4*)&g_xp[s3 * FF + lane * 4];
        acc.x += w0 * v0.x + w1 * v1.x + w2 * v2.x + w3 * v3.x;
        acc.y += w0 * v0.y + w1 * v1.y + w2 * v2.y + w3 * v3.y;
        acc.z += w0 * v0.z + w1 * v1.z + w2 * v2.z + w3 * v3.z;
        acc.w += w0 * v0.w + w1 * v1.w + w2 * v2.w + w3 * v3.w;
    }
    for (; i < re; i++) {
        int s0 = g_csrc[i];
        float w0 = __expf(abase[i * 4 + h] - mh) * ih;
        float4 v0 = *(const float4*)&g_xp[s0 * FF + lane * 4];
        acc.x += w0 * v0.x; acc.y += w0 * v0.y;
        acc.z += w0 * v0.z; acc.w += w0 * v0.w;
    }
    // self-loop contribution (own features)
    {
        float ws = wsl * ih;
        float4 v0 = *(const float4*)&g_xp[n * FF + lane * 4];
        acc.x += ws * v0.x; acc.y += ws * v0.y;
        acc.z += ws * v0.z; acc.w += ws * v0.w;
    }
    // ELU(out + bias)
    float4 b = *(const float4*)&bias[lane * 4];
    float r0 = acc.x + b.x, r1 = acc.y + b.y, r2 = acc.z + b.z, r3 = acc.w + b.w;
    r0 = r0 > 0.f ? r0 : expm1f(r0);
    r1 = r1 > 0.f ? r1 : expm1f(r1);
    r2 = r2 > 0.f ? r2 : expm1f(r2);
    r3 = r3 > 0.f ? r3 : expm1f(r3);
    *(float4*)&g_h[n * FF + lane * 4] = make_float4(r0, r1, r2, r3);
}

// ---------------- K6: fused MLP via tf32 tensor cores ----------------
// smem: sW1[128][128] + sW2[128][32] + shA[64][132] + sh1[64][132]
#define MLP_SMEM (16384*4 + 4096*4 + 8448*4 + 8448*4)
__global__ void k_mlp(const float* __restrict__ W1, const float* __restrict__ b1,
                      const float* __restrict__ pa, const float* __restrict__ W2,
                      const float* __restrict__ b2, float* __restrict__ out) {
    extern __shared__ float smem[];
    float* sW1 = smem;              // [128][128]
    float* sW2 = sW1 + 16384;       // [128][32]
    float* shA = sW2 + 4096;        // [64][132]  input h (then layer-2 output)
    float* sh1 = shA + 8448;        // [64][132]  hidden h1
    int t = threadIdx.x;
    int w = t >> 5;
    int m0 = blockIdx.x * 64;

    for (int i = t; i < 16384; i += 256) sW1[i] = W1[i];
    for (int i = t; i < 4096; i += 256)  sW2[i] = W2[i];
    for (int i = t; i < 64 * 128; i += 256) {
        int r = i >> 7, k = i & 127;
        int node = m0 + r;
        shA[r * 132 + k] = (node < N_NODES) ? g_h[node * 128 + k] : 0.f;
    }
    float prelu = pa[0];
    __syncthreads();

    // ---- layer 1: [64x128] @ [128x128]; 8 warps, each a 32x32 tile ----
    {
        int wr = w >> 2, wc = w & 3;
        wm::fragment<wm::accumulator, 16, 16, 8, float> acc[2][2];
#pragma unroll
        for (int i = 0; i < 2; i++)
#pragma unroll
            for (int j = 0; j < 2; j++) wm::fill_fragment(acc[i][j], 0.f);
        for (int k = 0; k < 128; k += 8) {
            wm::fragment<wm::matrix_a, 16, 16, 8, wm::precision::tf32, wm::row_major> a[2];
            wm::fragment<wm::matrix_b, 16, 16, 8, wm::precision::tf32, wm::row_major> b[2];
#pragma unroll
            for (int i = 0; i < 2; i++) {
                wm::load_matrix_sync(a[i], &shA[(wr * 32 + i * 16) * 132 + k], 132);
#pragma unroll
                for (int e = 0; e < a[i].num_elements; e++) a[i].x[e] = wm::__float_to_tf32(a[i].x[e]);
            }
#pragma unroll
            for (int j = 0; j < 2; j++) {
                wm::load_matrix_sync(b[j], &sW1[k * 128 + wc * 32 + j * 16], 128);
#pragma unroll
                for (int e = 0; e < b[j].num_elements; e++) b[j].x[e] = wm::__float_to_tf32(b[j].x[e]);
            }
#pragma unroll
            for (int i = 0; i < 2; i++)
#pragma unroll
                for (int j = 0; j < 2; j++)
                    wm::mma_sync(acc[i][j], a[i], b[j], acc[i][j]);
        }
#pragma unroll
        for (int i = 0; i < 2; i++)
#pragma unroll
            for (int j = 0; j < 2; j++)
                wm::store_matrix_sync(&sh1[(wr * 32 + i * 16) * 132 + wc * 32 + j * 16],
                                      acc[i][j], 132, wm::mem_row_major);
    }
    __syncthreads();
    // bias + PReLU in place
    for (int i = t; i < 64 * 128; i += 256) {
        int r = i >> 7, c = i & 127;
        float v = sh1[r * 132 + c] + b1[c];
        sh1[r * 132 + c] = v > 0.f ? v : prelu * v;
    }
    __syncthreads();
    // ---- layer 2: [64x128] @ [128x32]; 8 warps, each one 16x16 tile ----
    {
        int wr = w >> 1, wc = w & 1;
        wm::fragment<wm::accumulator, 16, 16, 8, float> acc;
        wm::fill_fragment(acc, 0.f);
        for (int k = 0; k < 128; k += 8) {
            wm::fragment<wm::matrix_a, 16, 16, 8, wm::precision::tf32, wm::row_major> a;
            wm::fragment<wm::matrix_b, 16, 16, 8, wm::precision::tf32, wm::row_major> b;
            wm::load_matrix_sync(a, &sh1[(wr * 16) * 132 + k], 132);
#pragma unroll
            for (int e = 0; e < a.num_elements; e++) a.x[e] = wm::__float_to_tf32(a.x[e]);
            wm::load_matrix_sync(b, &sW2[k * 32 + wc * 16], 32);
#pragma unroll
            for (int e = 0; e < b.num_elements; e++) b.x[e] = wm::__float_to_tf32(b.x[e]);
            wm::mma_sync(acc, a, b, acc);
        }
        wm::store_matrix_sync(&shA[(wr * 16) * 132 + wc * 16], acc, 132, wm::mem_row_major);
    }
    __syncthreads();
    // write out with b2
    for (int i = t; i < 64 * 32; i += 256) {
        int r = i >> 5, c = i & 31;
        int node = m0 + r;
        if (node < N_NODES) out[node * 32 + c] = shA[r * 132 + c] + b2[c];
    }
}

// ---------------- launch ----------------
extern "C" void kernel_launch(void* const* d_in, const int* in_sizes, int n_in,
                              void* d_out, int out_size) {
    const float*     x        = (const float*)d_in[0];
    const void*      ei       = d_in[1];
    const float*     ea       = (const float*)d_in[2];
    const float*     W_gat    = (const float*)d_in[3];
    const float*     att_src  = (const float*)d_in[4];
    const float*     att_dst  = (const float*)d_in[5];
    const float*     W_edge   = (const float*)d_in[6];
    const float*     att_edge = (const float*)d_in[7];
    const float*     bias_gat = (const float*)d_in[8];
    const float*     W1       = (const float*)d_in[9];
    const float*     b1       = (const float*)d_in[10];
    const float*     prelu_a  = (const float*)d_in[11];
    const float*     W2       = (const float*)d_in[12];
    const float*     b2       = (const float*)d_in[13];
    float*           out      = (float*)d_out;

    cudaFuncSetAttribute(k_mlp, cudaFuncAttributeMaxDynamicSharedMemorySize, MLP_SMEM);

    k_init<<<(N_NODES + 255) / 256, 256>>>((const int*)ei, W_edge, att_edge);
    k_deg<<<(NE + 255) / 256, 256>>>(ei, ea);
    k_node<<<(N_NODES * 32 + 255) / 256, 256>>>(x, W_gat, att_src, att_dst);
    k_scan<<<SCAN_BLOCKS, 1024>>>();
    k_edge<<<(NE + 255) / 256, 256>>>(ei, ea);
    k_agg<<<(N_NODES * 32 + 255) / 256, 256>>>(bias_gat);
    k_mlp<<<(N_NODES + 63) / 64, 256, MLP_SMEM>>>(W1, b1, prelu_a, W2, b2, out);
}

// round 10
// speedup vs baseline: 1.4283x; 1.1028x over previous
#include <cuda_runtime.h>
#include <cuda_fp16.h>
#include <math.h>
#include <mma.h>

namespace wm = nvcuda::wmma;

#define N_NODES 50000
#define NE      1600000
#define HH      4
#define CC      32
#define FF      128                // HH*CC
#define NEG_SLOPE 0.2f
#define SCAN_BLOCKS 13             // ceil(50000 / 4096)

// ---------------- scratch (device globals; no allocations allowed) ----------------
__device__ __align__(16) __half g_xph[N_NODES * FF];    // projected features fp16 [N,128]
__device__ __align__(16) float  g_asrc[N_NODES * 4];
__device__ __align__(16) float  g_adst[N_NODES * 4];
__device__ __align__(16) float  g_aesum[N_NODES * 4];   // folded edge-att segment sum (per head)
__device__ __align__(16) int    g_deg[N_NODES];
__device__ __align__(16) int    g_rowptr[N_NODES + 4];
__device__ __align__(16) int    g_wptr[N_NODES + 4];
__device__ int    g_csrc[NE];
__device__ float4 g_calpha[NE];
__device__ __align__(16) float  g_h[N_NODES * FF];      // ELU(out+bias) hidden
__device__ float  g_M[7 * 4];                           // folded edge attention matrix
__device__ int    g_is64;                               // edge_index dtype flag
__device__ unsigned g_scanstate[SCAN_BLOCKS];

__device__ __forceinline__ float lrelu(float v) { return v > 0.f ? v : NEG_SLOPE * v; }

// index accessor that works for both int32 and int64 edge_index
__device__ __forceinline__ int ld_idx(const void* ei, int pos) {
    if (g_is64) return (int)((const long long*)ei)[pos];
    return ((const int*)ei)[pos];
}

__device__ __forceinline__ void red_add_v4(float* p, float4 v) {
    asm volatile("red.global.add.v4.f32 [%0], {%1,%2,%3,%4};"
                 :: "l"(p), "f"(v.x), "f"(v.y), "f"(v.z), "f"(v.w) : "memory");
}

// ---------------- K0: zero counters + dtype detect + fold M (merged) ----------------
__global__ void k_init(const int* __restrict__ ei_w, const float* __restrict__ W_edge,
                       const float* __restrict__ att_edge) {
    int t = blockIdx.x * blockDim.x + threadIdx.x;
    if (t < N_NODES) {
        g_deg[t] = 0;
        *(float4*)&g_aesum[t * 4] = make_float4(0.f, 0.f, 0.f, 0.f);
    }
    if (blockIdx.x == 0) {
        __shared__ int ok[2];
        int tt = threadIdx.x;
        if (tt < SCAN_BLOCKS) g_scanstate[tt] = 0u;
        if (tt < 64) {
            // int64 little-endian values < 2^31 have zero high words at odd 32-bit offsets
            int v = ei_w[2 * tt + 1];
            unsigned ball = __ballot_sync(0xFFFFFFFFu, v == 0);
            if ((tt & 31) == 0) ok[tt >> 5] = (ball == 0xFFFFFFFFu) ? 1 : 0;
        }
        __syncthreads();
        if (tt == 0) g_is64 = ok[0] & ok[1];
        if (tt < 28) {
            int k = tt >> 2, h = tt & 3;
            float s = 0.f;
            for (int c = 0; c < CC; c++) s += W_edge[k * FF + h * CC + c] * att_edge[h * CC + c];
            g_M[k * 4 + h] = s;
        }
    }
}

// ---------------- K1: in-degree + folded edge-attention segment sum ----------------
__global__ void k_deg(const void* __restrict__ ei, const float* __restrict__ ea) {
    int e = blockIdx.x * blockDim.x + threadIdx.x;
    if (e >= NE) return;
    int dst = ld_idx(ei, NE + e);
    atomicAdd(&g_deg[dst], 1);
    float ev[7];
#pragma unroll
    for (int k = 0; k < 7; k++) ev[k] = ea[e * 7 + k];
    float4 s4;
    float* s = (float*)&s4;
#pragma unroll
    for (int h = 0; h < 4; h++) {
        float s0 = 0.f;
#pragma unroll
        for (int k = 0; k < 7; k++) s0 = fmaf(ev[k], g_M[k * 4 + h], s0);
        s[h] = s0;
    }
    red_add_v4(&g_aesum[dst * 4], s4);
}

// ---------------- K2: per-node projection + a_src/a_dst ----------------
__global__ void k_node(const float* __restrict__ x, const float* __restrict__ W_gat,
                       const float* __restrict__ att_src, const float* __restrict__ att_dst) {
    int warp = (blockIdx.x * blockDim.x + threadIdx.x) >> 5;
    int lane = threadIdx.x & 31;
    if (warp >= N_NODES) return;
    int n = warp;
    float x0 = x[n * 3 + 0], x1 = x[n * 3 + 1], x2 = x[n * 3 + 2];
    int i0 = lane * 4;
    float v[4];
    float as = 0.f, ad = 0.f;
#pragma unroll
    for (int j = 0; j < 4; j++) {
        int i = i0 + j;
        float p = fmaf(x0, W_gat[i], fmaf(x1, W_gat[FF + i], x2 * W_gat[2 * FF + i]));
        v[j] = p;
        as = fmaf(p, att_src[i], as);
        ad = fmaf(p, att_dst[i], ad);
    }
    __half2 h0 = __floats2half2_rn(v[0], v[1]);
    __half2 h1 = __floats2half2_rn(v[2], v[3]);
    uint2 u;
    u.x = *(unsigned*)&h0;
    u.y = *(unsigned*)&h1;
    *(uint2*)&g_xph[n * FF + i0] = u;
    // reduce within each 8-lane group (one group per head)
#pragma unroll
    for (int o = 1; o < 8; o <<= 1) {
        as += __shfl_xor_sync(0xFFFFFFFFu, as, o);
        ad += __shfl_xor_sync(0xFFFFFFFFu, ad, o);
    }
    int h = lane >> 3;
    if ((lane & 7) == 0) {
        g_asrc[n * 4 + h] = as;
        g_adst[n * 4 + h] = ad;
    }
}

// ---------------- K3: single-pass decoupled-lookback exclusive scan of deg ----------------
__global__ void k_scan() {
    __shared__ int wsum[32];
    __shared__ int s_prefix;
    int bid = blockIdx.x;
    int t = threadIdx.x, lane = t & 31, w = t >> 5;
    int i0 = bid * 4096 + t * 4;
    int v0 = 0, v1 = 0, v2 = 0, v3 = 0;
    if (i0 < N_NODES) {   // N_NODES % 4 == 0 -> full int4 in-bounds
        int4 d = *(const int4*)&g_deg[i0];
        v0 = d.x; v1 = d.y; v2 = d.z; v3 = d.w;
    }
    int tsum = v0 + v1 + v2 + v3;
    int s = tsum;
#pragma unroll
    for (int o = 1; o < 32; o <<= 1) {
        int u = __shfl_up_sync(0xFFFFFFFFu, s, o);
        if (lane >= o) s += u;
    }
    if (lane == 31) wsum[w] = s;
    __syncthreads();
    if (w == 0) {
        int ws = wsum[lane];
#pragma unroll
        for (int o = 1; o < 32; o <<= 1) {
            int u = __shfl_up_sync(0xFFFFFFFFu, ws, o);
            if (lane >= o) ws += u;
        }
        wsum[lane] = ws;
    }
    __syncthreads();
    int excl = (w > 0 ? wsum[w - 1] : 0) + s - tsum;
    int agg = wsum[31];
    if (t == 0) {
        unsigned pub = (bid == 0) ? (0x80000000u | (unsigned)agg) : (0x40000000u | (unsigned)agg);
        atomicExch(&g_scanstate[bid], pub);
        int prefix = 0;
        if (bid > 0) {
            for (int j = bid - 1; j >= 0; ) {
                unsigned st;
                do { st = atomicAdd(&g_scanstate[j], 0u); } while (st == 0u);
                prefix += (int)(st & 0x3FFFFFFFu);
                if (st & 0x80000000u) break;
                j--;
            }
            atomicExch(&g_scanstate[bid], 0x80000000u | (unsigned)(prefix + agg));
        }
        s_prefix = prefix;
        if (bid == SCAN_BLOCKS - 1) g_rowptr[N_NODES] = prefix + agg;
    }
    __syncthreads();
    int base = s_prefix + excl;
    if (i0 < N_NODES) {
        int4 r;
        r.x = base; r.y = base + v0; r.z = base + v0 + v1; r.w = base + v0 + v1 + v2;
        *(int4*)&g_rowptr[i0] = r;
        *(int4*)&g_wptr[i0] = r;
    }
}

// ---------------- K4: per-edge alpha + CSR scatter (real edges only) ----------------
__global__ void k_edge(const void* __restrict__ ei, const float* __restrict__ ea) {
    int t = blockIdx.x * blockDim.x + threadIdx.x;
    if (t >= NE) return;
    int src = ld_idx(ei, t);
    int dst = ld_idx(ei, NE + t);
    float e[7];
#pragma unroll
    for (int k = 0; k < 7; k++) e[k] = ea[t * 7 + k];
    float ah[4];
#pragma unroll
    for (int h = 0; h < 4; h++) {
        float s = 0.f;
#pragma unroll
        for (int k = 0; k < 7; k++) s = fmaf(e[k], g_M[k * 4 + h], s);
        ah[h] = s;
    }
    float4 as = *(const float4*)&g_asrc[src * 4];
    float4 ad = *(const float4*)&g_adst[dst * 4];
    float4 a4;
    a4.x = lrelu(as.x + ad.x + ah[0]);
    a4.y = lrelu(as.y + ad.y + ah[1]);
    a4.z = lrelu(as.z + ad.z + ah[2]);
    a4.w = lrelu(as.w + ad.w + ah[3]);
    int pos = atomicAdd(&g_wptr[dst], 1);
    g_csrc[pos] = src;
    g_calpha[pos] = a4;
}

// ---------------- K5: single-pass softmax + aggregation (shift by self-loop logit) ----------------
__global__ void k_agg(const float* __restrict__ bias) {
    int warp = (blockIdx.x * blockDim.x + threadIdx.x) >> 5;
    int lane = threadIdx.x & 31;
    if (warp >= N_NODES) return;
    int n = warp;
    int rs = g_rowptr[n], re = g_rowptr[n + 1];
    int deg = re - rs;

    // self-loop logit (same in every lane)
    float4 as4 = *(const float4*)&g_asrc[n * 4];
    float4 ad4 = *(const float4*)&g_adst[n * 4];
    float4 ae4 = *(const float4*)&g_aesum[n * 4];
    float invd = 1.0f / fmaxf((float)deg, 1.0f);
    float4 asl;
    asl.x = lrelu(as4.x + ad4.x + ae4.x * invd);
    asl.y = lrelu(as4.y + ad4.y + ae4.y * invd);
    asl.z = lrelu(as4.z + ad4.z + ae4.z * invd);
    asl.w = lrelu(as4.w + ad4.w + ae4.w * invd);

    int h = lane >> 3;
    float aslh = (h == 0) ? asl.x : (h == 1) ? asl.y : (h == 2) ? asl.z : asl.w;

    // seed with self-loop: weight exp(asl - asl) = 1
    float dh = 1.0f;
    float4 acc;
    {
        uint2 u = *(const uint2*)&g_xph[n * FF + lane * 4];
        float2 f01 = __half22float2(*(__half2*)&u.x);
        float2 f23 = __half22float2(*(__half2*)&u.y);
        acc = make_float4(f01.x, f01.y, f23.x, f23.y);
    }

    const float* abase = (const float*)g_calpha;
    int i = rs;
    for (; i + 4 <= re; i += 4) {
        int s0 = g_csrc[i + 0], s1 = g_csrc[i + 1], s2 = g_csrc[i + 2], s3 = g_csrc[i + 3];
        float w0 = __expf(abase[(i + 0) * 4 + h] - aslh);
        float w1 = __expf(abase[(i + 1) * 4 + h] - aslh);
        float w2 = __expf(abase[(i + 2) * 4 + h] - aslh);
        float w3 = __expf(abase[(i + 3) * 4 + h] - aslh);
        dh += w0 + w1 + w2 + w3;
        uint2 u0 = *(const uint2*)&g_xph[s0 * FF + lane * 4];
        uint2 u1 = *(const uint2*)&g_xph[s1 * FF + lane * 4];
        uint2 u2 = *(const uint2*)&g_xph[s2 * FF + lane * 4];
        uint2 u3 = *(const uint2*)&g_xph[s3 * FF + lane * 4];
        float2 a01 = __half22float2(*(__half2*)&u0.x), a23 = __half22float2(*(__half2*)&u0.y);
        float2 b01 = __half22float2(*(__half2*)&u1.x), b23 = __half22float2(*(__half2*)&u1.y);
        float2 c01 = __half22float2(*(__half2*)&u2.x), c23 = __half22float2(*(__half2*)&u2.y);
        float2 d01 = __half22float2(*(__half2*)&u3.x), d23 = __half22float2(*(__half2*)&u3.y);
        acc.x += w0 * a01.x + w1 * b01.x + w2 * c01.x + w3 * d01.x;
        acc.y += w0 * a01.y + w1 * b01.y + w2 * c01.y + w3 * d01.y;
        acc.z += w0 * a23.x + w1 * b23.x + w2 * c23.x + w3 * d23.x;
        acc.w += w0 * a23.y + w1 * b23.y + w2 * c23.y + w3 * d23.y;
    }
    for (; i < re; i++) {
        int s0 = g_csrc[i];
        float w0 = __expf(abase[i * 4 + h] - aslh);
        dh += w0;
        uint2 u0 = *(const uint2*)&g_xph[s0 * FF + lane * 4];
        float2 a01 = __half22float2(*(__half2*)&u0.x), a23 = __half22float2(*(__half2*)&u0.y);
        acc.x += w0 * a01.x; acc.y += w0 * a01.y;
        acc.z += w0 * a23.x; acc.w += w0 * a23.y;
    }
    float ih = 1.0f / dh;

    // ELU(out + bias)
    float4 b = *(const float4*)&bias[lane * 4];
    float r0 = acc.x * ih + b.x, r1 = acc.y * ih + b.y;
    float r2 = acc.z * ih + b.z, r3 = acc.w * ih + b.w;
    r0 = r0 > 0.f ? r0 : expm1f(r0);
    r1 = r1 > 0.f ? r1 : expm1f(r1);
    r2 = r2 > 0.f ? r2 : expm1f(r2);
    r3 = r3 > 0.f ? r3 : expm1f(r3);
    *(float4*)&g_h[n * FF + lane * 4] = make_float4(r0, r1, r2, r3);
}

// ---------------- K6: fused MLP via tf32 tensor cores ----------------
// smem: sW1[128][128] + sW2[128][32] + shA[64][132] + sh1[64][132]
#define MLP_SMEM (16384*4 + 4096*4 + 8448*4 + 8448*4)
__global__ void k_mlp(const float* __restrict__ W1, const float* __restrict__ b1,
                      const float* __restrict__ pa, const float* __restrict__ W2,
                      const float* __restrict__ b2, float* __restrict__ out) {
    extern __shared__ float smem[];
    float* sW1 = smem;              // [128][128]
    float* sW2 = sW1 + 16384;       // [128][32]
    float* shA = sW2 + 4096;        // [64][132]  input h (then layer-2 output)
    float* sh1 = shA + 8448;        // [64][132]  hidden h1
    int t = threadIdx.x;
    int w = t >> 5;
    int m0 = blockIdx.x * 64;

    for (int i = t; i < 16384; i += 256) sW1[i] = W1[i];
    for (int i = t; i < 4096; i += 256)  sW2[i] = W2[i];
    for (int i = t; i < 64 * 128; i += 256) {
        int r = i >> 7, k = i & 127;
        int node = m0 + r;
        shA[r * 132 + k] = (node < N_NODES) ? g_h[node * 128 + k] : 0.f;
    }
    float prelu = pa[0];
    __syncthreads();

    // ---- layer 1: [64x128] @ [128x128]; 8 warps, each a 32x32 tile ----
    {
        int wr = w >> 2, wc = w & 3;
        wm::fragment<wm::accumulator, 16, 16, 8, float> acc[2][2];
#pragma unroll
        for (int i = 0; i < 2; i++)
#pragma unroll
            for (int j = 0; j < 2; j++) wm::fill_fragment(acc[i][j], 0.f);
        for (int k = 0; k < 128; k += 8) {
            wm::fragment<wm::matrix_a, 16, 16, 8, wm::precision::tf32, wm::row_major> a[2];
            wm::fragment<wm::matrix_b, 16, 16, 8, wm::precision::tf32, wm::row_major> b[2];
#pragma unroll
            for (int i = 0; i < 2; i++) {
                wm::load_matrix_sync(a[i], &shA[(wr * 32 + i * 16) * 132 + k], 132);
#pragma unroll
                for (int e = 0; e < a[i].num_elements; e++) a[i].x[e] = wm::__float_to_tf32(a[i].x[e]);
            }
#pragma unroll
            for (int j = 0; j < 2; j++) {
                wm::load_matrix_sync(b[j], &sW1[k * 128 + wc * 32 + j * 16], 128);
#pragma unroll
                for (int e = 0; e < b[j].num_elements; e++) b[j].x[e] = wm::__float_to_tf32(b[j].x[e]);
            }
#pragma unroll
            for (int i = 0; i < 2; i++)
#pragma unroll
                for (int j = 0; j < 2; j++)
                    wm::mma_sync(acc[i][j], a[i], b[j], acc[i][j]);
        }
#pragma unroll
        for (int i = 0; i < 2; i++)
#pragma unroll
            for (int j = 0; j < 2; j++)
                wm::store_matrix_sync(&sh1[(wr * 32 + i * 16) * 132 + wc * 32 + j * 16],
                                      acc[i][j], 132, wm::mem_row_major);
    }
    __syncthreads();
    // bias + PReLU in place
    for (int i = t; i < 64 * 128; i += 256) {
        int r = i >> 7, c = i & 127;
        float v = sh1[r * 132 + c] + b1[c];
        sh1[r * 132 + c] = v > 0.f ? v : prelu * v;
    }
    __syncthreads();
    // ---- layer 2: [64x128] @ [128x32]; 8 warps, each one 16x16 tile ----
    {
        int wr = w >> 1, wc = w & 1;
        wm::fragment<wm::accumulator, 16, 16, 8, float> acc;
        wm::fill_fragment(acc, 0.f);
        for (int k = 0; k < 128; k += 8) {
            wm::fragment<wm::matrix_a, 16, 16, 8, wm::precision::tf32, wm::row_major> a;
            wm::fragment<wm::matrix_b, 16, 16, 8, wm::precision::tf32, wm::row_major> b;
            wm::load_matrix_sync(a, &sh1[(wr * 16) * 132 + k], 132);
#pragma unroll
            for (int e = 0; e < a.num_elements; e++) a.x[e] = wm::__float_to_tf32(a.x[e]);
            wm::load_matrix_sync(b, &sW2[k * 32 + wc * 16], 32);
#pragma unroll
            for (int e = 0; e < b.num_elements; e++) b.x[e] = wm::__float_to_tf32(b.x[e]);
            wm::mma_sync(acc, a, b, acc);
        }
        wm::store_matrix_sync(&shA[(wr * 16) * 132 + wc * 16], acc, 132, wm::mem_row_major);
    }
    __syncthreads();
    // write out with b2
    for (int i = t; i < 64 * 32; i += 256) {
        int r = i >> 5, c = i & 31;
        int node = m0 + r;
        if (node < N_NODES) out[node * 32 + c] = shA[r * 132 + c] + b2[c];
    }
}

// ---------------- launch ----------------
extern "C" void kernel_launch(void* const* d_in, const int* in_sizes, int n_in,
                              void* d_out, int out_size) {
    const float*     x        = (const float*)d_in[0];
    const void*      ei       = d_in[1];
    const float*     ea       = (const float*)d_in[2];
    const float*     W_gat    = (const float*)d_in[3];
    const float*     att_src  = (const float*)d_in[4];
    const float*     att_dst  = (const float*)d_in[5];
    const float*     W_edge   = (const float*)d_in[6];
    const float*     att_edge = (const float*)d_in[7];
    const float*     bias_gat = (const float*)d_in[8];
    const float*     W1       = (const float*)d_in[9];
    const float*     b1       = (const float*)d_in[10];
    const float*     prelu_a  = (const float*)d_in[11];
    const float*     W2       = (const float*)d_in[12];
    const float*     b2       = (const float*)d_in[13];
    float*           out      = (float*)d_out;

    cudaFuncSetAttribute(k_mlp, cudaFuncAttributeMaxDynamicSharedMemorySize, MLP_SMEM);

    k_init<<<(N_NODES + 255) / 256, 256>>>((const int*)ei, W_edge, att_edge);
    k_deg<<<(NE + 255) / 256, 256>>>(ei, ea);
    k_node<<<(N_NODES * 32 + 255) / 256, 256>>>(x, W_gat, att_src, att_dst);
    k_scan<<<SCAN_BLOCKS, 1024>>>();
    k_edge<<<(NE + 255) / 256, 256>>>(ei, ea);
    k_agg<<<(N_NODES * 32 + 255) / 256, 256>>>(bias_gat);
    k_mlp<<<(N_NODES + 63) / 64, 256, MLP_SMEM>>>(W1, b1, prelu_a, W2, b2, out);
}

// round 13
// speedup vs baseline: 1.4551x; 1.0188x over previous
#include <cuda_runtime.h>
#include <cuda_fp16.h>
#include <math.h>
#include <mma.h>

namespace wm = nvcuda::wmma;

#define N_NODES 50000
#define NE      1600000
#define HH      4
#define CC      32
#define FF      128                // HH*CC
#define NEG_SLOPE 0.2f
#define SCAN_BLOCKS 13             // ceil(50000 / 4096)

// ---------------- scratch (device globals; no allocations allowed) ----------------
__device__ __align__(16) __half g_xph[N_NODES * FF];    // projected features fp16 [N,128]
__device__ __align__(16) float  g_asrc[N_NODES * 4];
__device__ __align__(16) float  g_adst[N_NODES * 4];
__device__ __align__(16) float  g_aesum[N_NODES * 4];   // folded edge-att segment sum (per head)
__device__ __align__(16) int    g_deg[N_NODES];
__device__ __align__(16) int    g_rowptr[N_NODES + 4];
__device__ __align__(16) int    g_wptr[N_NODES + 4];
__device__ int    g_csrc[NE];
__device__ float4 g_calpha[NE];
__device__ __align__(16) float  g_h[N_NODES * FF];      // ELU(out+bias) hidden
__device__ float  g_M[7 * 4];                           // folded edge attention matrix
__device__ int    g_is64;                               // edge_index dtype flag
__device__ unsigned g_scanstate[SCAN_BLOCKS];

__device__ __forceinline__ float lrelu(float v) { return v > 0.f ? v : NEG_SLOPE * v; }

// index accessor that works for both int32 and int64 edge_index
__device__ __forceinline__ int ld_idx(const void* ei, int pos) {
    if (g_is64) return (int)((const long long*)ei)[pos];
    return ((const int*)ei)[pos];
}

__device__ __forceinline__ void red_add_v4(float* p, float4 v) {
    asm volatile("red.global.add.v4.f32 [%0], {%1,%2,%3,%4};"
                 :: "l"(p), "f"(v.x), "f"(v.y), "f"(v.z), "f"(v.w) : "memory");
}

// ---------------- K0: zero counters + dtype detect + fold M (merged) ----------------
__global__ void k_init(const int* __restrict__ ei_w, const float* __restrict__ W_edge,
                       const float* __restrict__ att_edge) {
    int t = blockIdx.x * blockDim.x + threadIdx.x;
    if (t < N_NODES) {
        g_deg[t] = 0;
        *(float4*)&g_aesum[t * 4] = make_float4(0.f, 0.f, 0.f, 0.f);
    }
    if (blockIdx.x == 0) {
        __shared__ int ok[2];
        int tt = threadIdx.x;
        if (tt < SCAN_BLOCKS) g_scanstate[tt] = 0u;
        if (tt < 64) {
            // int64 little-endian values < 2^31 have zero high words at odd 32-bit offsets
            int v = ei_w[2 * tt + 1];
            unsigned ball = __ballot_sync(0xFFFFFFFFu, v == 0);
            if ((tt & 31) == 0) ok[tt >> 5] = (ball == 0xFFFFFFFFu) ? 1 : 0;
        }
        __syncthreads();
        if (tt == 0) g_is64 = ok[0] & ok[1];
        if (tt < 28) {
            int k = tt >> 2, h = tt & 3;
            float s = 0.f;
            for (int c = 0; c < CC; c++) s += W_edge[k * FF + h * CC + c] * att_edge[h * CC + c];
            g_M[k * 4 + h] = s;
        }
    }
}

// ---------------- K1: in-degree only (aesum moved into k_edge) ----------------
__global__ void k_deg(const void* __restrict__ ei) {
    int e = blockIdx.x * blockDim.x + threadIdx.x;
    if (e >= NE) return;
    int dst = ld_idx(ei, NE + e);
    atomicAdd(&g_deg[dst], 1);
}

// ---------------- K2: per-node projection + a_src/a_dst ----------------
__global__ void k_node(const float* __restrict__ x, const float* __restrict__ W_gat,
                       const float* __restrict__ att_src, const float* __restrict__ att_dst) {
    int warp = (blockIdx.x * blockDim.x + threadIdx.x) >> 5;
    int lane = threadIdx.x & 31;
    if (warp >= N_NODES) return;
    int n = warp;
    float x0 = x[n * 3 + 0], x1 = x[n * 3 + 1], x2 = x[n * 3 + 2];
    int i0 = lane * 4;
    float v[4];
    float as = 0.f, ad = 0.f;
#pragma unroll
    for (int j = 0; j < 4; j++) {
        int i = i0 + j;
        float p = fmaf(x0, W_gat[i], fmaf(x1, W_gat[FF + i], x2 * W_gat[2 * FF + i]));
        v[j] = p;
        as = fmaf(p, att_src[i], as);
        ad = fmaf(p, att_dst[i], ad);
    }
    __half2 h0 = __floats2half2_rn(v[0], v[1]);
    __half2 h1 = __floats2half2_rn(v[2], v[3]);
    uint2 u;
    u.x = *(unsigned*)&h0;
    u.y = *(unsigned*)&h1;
    *(uint2*)&g_xph[n * FF + i0] = u;
    // reduce within each 8-lane group (one group per head)
#pragma unroll
    for (int o = 1; o < 8; o <<= 1) {
        as += __shfl_xor_sync(0xFFFFFFFFu, as, o);
        ad += __shfl_xor_sync(0xFFFFFFFFu, ad, o);
    }
    int h = lane >> 3;
    if ((lane & 7) == 0) {
        g_asrc[n * 4 + h] = as;
        g_adst[n * 4 + h] = ad;
    }
}

// ---------------- K3: single-pass decoupled-lookback exclusive scan of deg ----------------
__global__ void k_scan() {
    __shared__ int wsum[32];
    __shared__ int s_prefix;
    int bid = blockIdx.x;
    int t = threadIdx.x, lane = t & 31, w = t >> 5;
    int i0 = bid * 4096 + t * 4;
    int v0 = 0, v1 = 0, v2 = 0, v3 = 0;
    if (i0 < N_NODES) {   // N_NODES % 4 == 0 -> full int4 in-bounds
        int4 d = *(const int4*)&g_deg[i0];
        v0 = d.x; v1 = d.y; v2 = d.z; v3 = d.w;
    }
    int tsum = v0 + v1 + v2 + v3;
    int s = tsum;
#pragma unroll
    for (int o = 1; o < 32; o <<= 1) {
        int u = __shfl_up_sync(0xFFFFFFFFu, s, o);
        if (lane >= o) s += u;
    }
    if (lane == 31) wsum[w] = s;
    __syncthreads();
    if (w == 0) {
        int ws = wsum[lane];
#pragma unroll
        for (int o = 1; o < 32; o <<= 1) {
            int u = __shfl_up_sync(0xFFFFFFFFu, ws, o);
            if (lane >= o) ws += u;
        }
        wsum[lane] = ws;
    }
    __syncthreads();
    int excl = (w > 0 ? wsum[w - 1] : 0) + s - tsum;
    int agg = wsum[31];
    if (t == 0) {
        unsigned pub = (bid == 0) ? (0x80000000u | (unsigned)agg) : (0x40000000u | (unsigned)agg);
        atomicExch(&g_scanstate[bid], pub);
        int prefix = 0;
        if (bid > 0) {
            for (int j = bid - 1; j >= 0; ) {
                unsigned st;
                do { st = atomicAdd(&g_scanstate[j], 0u); } while (st == 0u);
                prefix += (int)(st & 0x3FFFFFFFu);
                if (st & 0x80000000u) break;
                j--;
            }
            atomicExch(&g_scanstate[bid], 0x80000000u | (unsigned)(prefix + agg));
        }
        s_prefix = prefix;
        if (bid == SCAN_BLOCKS - 1) g_rowptr[N_NODES] = prefix + agg;
    }
    __syncthreads();
    int base = s_prefix + excl;
    if (i0 < N_NODES) {
        int4 r;
        r.x = base; r.y = base + v0; r.z = base + v0 + v1; r.w = base + v0 + v1 + v2;
        *(int4*)&g_rowptr[i0] = r;
        *(int4*)&g_wptr[i0] = r;
    }
}

// ---------------- K4: per-edge alpha + CSR scatter + aesum accumulation ----------------
__global__ void k_edge(const void* __restrict__ ei, const float* __restrict__ ea) {
    int t = blockIdx.x * blockDim.x + threadIdx.x;
    if (t >= NE) return;
    int src = ld_idx(ei, t);
    int dst = ld_idx(ei, NE + t);
    float e[7];
#pragma unroll
    for (int k = 0; k < 7; k++) e[k] = ea[t * 7 + k];
    float4 ah4;
    float* ah = (float*)&ah4;
#pragma unroll
    for (int h = 0; h < 4; h++) {
        float s = 0.f;
#pragma unroll
        for (int k = 0; k < 7; k++) s = fmaf(e[k], g_M[k * 4 + h], s);
        ah[h] = s;
    }
    // segment-sum of folded edge attention (consumed later by k_agg self-loop)
    red_add_v4(&g_aesum[dst * 4], ah4);
    float4 as = *(const float4*)&g_asrc[src * 4];
    float4 ad = *(const float4*)&g_adst[dst * 4];
    float4 a4;
    a4.x = lrelu(as.x + ad.x + ah[0]);
    a4.y = lrelu(as.y + ad.y + ah[1]);
    a4.z = lrelu(as.z + ad.z + ah[2]);
    a4.w = lrelu(as.w + ad.w + ah[3]);
    int pos = atomicAdd(&g_wptr[dst], 1);
    g_csrc[pos] = src;
    g_calpha[pos] = a4;
}

// ---------------- K5: single-pass softmax + aggregation (shift by self-loop logit) ----------------
__global__ void k_agg(const float* __restrict__ bias) {
    int warp = (blockIdx.x * blockDim.x + threadIdx.x) >> 5;
    int lane = threadIdx.x & 31;
    if (warp >= N_NODES) return;
    int n = warp;
    int rs = g_rowptr[n], re = g_rowptr[n + 1];
    int deg = re - rs;

    // self-loop logit (same in every lane)
    float4 as4 = *(const float4*)&g_asrc[n * 4];
    float4 ad4 = *(const float4*)&g_adst[n * 4];
    float4 ae4 = *(const float4*)&g_aesum[n * 4];
    float invd = 1.0f / fmaxf((float)deg, 1.0f);
    float4 asl;
    asl.x = lrelu(as4.x + ad4.x + ae4.x * invd);
    asl.y = lrelu(as4.y + ad4.y + ae4.y * invd);
    asl.z = lrelu(as4.z + ad4.z + ae4.z * invd);
    asl.w = lrelu(as4.w + ad4.w + ae4.w * invd);

    int h = lane >> 3;
    float aslh = (h == 0) ? asl.x : (h == 1) ? asl.y : (h == 2) ? asl.z : asl.w;

    // seed with self-loop: weight exp(asl - asl) = 1
    float dh = 1.0f;
    float4 acc;
    {
        uint2 u = *(const uint2*)&g_xph[n * FF + lane * 4];
        float2 f01 = __half22float2(*(__half2*)&u.x);
        float2 f23 = __half22float2(*(__half2*)&u.y);
        acc = make_float4(f01.x, f01.y, f23.x, f23.y);
    }

    const float* abase = (const float*)g_calpha;
    int i = rs;
    for (; i + 4 <= re; i += 4) {
        int s0 = g_csrc[i + 0], s1 = g_csrc[i + 1], s2 = g_csrc[i + 2], s3 = g_csrc[i + 3];
        float w0 = __expf(abase[(i + 0) * 4 + h] - aslh);
        float w1 = __expf(abase[(i + 1) * 4 + h] - aslh);
        float w2 = __expf(abase[(i + 2) * 4 + h] - aslh);
        float w3 = __expf(abase[(i + 3) * 4 + h] - aslh);
        dh += w0 + w1 + w2 + w3;
        uint2 u0 = *(const uint2*)&g_xph[s0 * FF + lane * 4];
        uint2 u1 = *(const uint2*)&g_xph[s1 * FF + lane * 4];
        uint2 u2 = *(const uint2*)&g_xph[s2 * FF + lane * 4];
        uint2 u3 = *(const uint2*)&g_xph[s3 * FF + lane * 4];
        float2 a01 = __half22float2(*(__half2*)&u0.x), a23 = __half22float2(*(__half2*)&u0.y);
        float2 b01 = __half22float2(*(__half2*)&u1.x), b23 = __half22float2(*(__half2*)&u1.y);
        float2 c01 = __half22float2(*(__half2*)&u2.x), c23 = __half22float2(*(__half2*)&u2.y);
        float2 d01 = __half22float2(*(__half2*)&u3.x), d23 = __half22float2(*(__half2*)&u3.y);
        acc.x += w0 * a01.x + w1 * b01.x + w2 * c01.x + w3 * d01.x;
        acc.y += w0 * a01.y + w1 * b01.y + w2 * c01.y + w3 * d01.y;
        acc.z += w0 * a23.x + w1 * b23.x + w2 * c23.x + w3 * d23.x;
        acc.w += w0 * a23.y + w1 * b23.y + w2 * c23.y + w3 * d23.y;
    }
    for (; i < re; i++) {
        int s0 = g_csrc[i];
        float w0 = __expf(abase[i * 4 + h] - aslh);
        dh += w0;
        uint2 u0 = *(const uint2*)&g_xph[s0 * FF + lane * 4];
        float2 a01 = __half22float2(*(__half2*)&u0.x), a23 = __half22float2(*(__half2*)&u0.y);
        acc.x += w0 * a01.x; acc.y += w0 * a01.y;
        acc.z += w0 * a23.x; acc.w += w0 * a23.y;
    }
    float ih = 1.0f / dh;

    // ELU(out + bias)
    float4 b = *(const float4*)&bias[lane * 4];
    float r0 = acc.x * ih + b.x, r1 = acc.y * ih + b.y;
    float r2 = acc.z * ih + b.z, r3 = acc.w * ih + b.w;
    r0 = r0 > 0.f ? r0 : expm1f(r0);
    r1 = r1 > 0.f ? r1 : expm1f(r1);
    r2 = r2 > 0.f ? r2 : expm1f(r2);
    r3 = r3 > 0.f ? r3 : expm1f(r3);
    *(float4*)&g_h[n * FF + lane * 4] = make_float4(r0, r1, r2, r3);
}

// ---------------- K6: fused MLP via tf32 tensor cores ----------------
// smem: sW1[128][128] + sW2[128][32] + shA[64][132] + sh1[64][132]
#define MLP_SMEM (16384*4 + 4096*4 + 8448*4 + 8448*4)
__global__ void k_mlp(const float* __restrict__ W1, const float* __restrict__ b1,
                      const float* __restrict__ pa, const float* __restrict__ W2,
                      const float* __restrict__ b2, float* __restrict__ out) {
    extern __shared__ float smem[];
    float* sW1 = smem;              // [128][128]
    float* sW2 = sW1 + 16384;       // [128][32]
    float* shA = sW2 + 4096;        // [64][132]  input h (then layer-2 output)
    float* sh1 = shA + 8448;        // [64][132]  hidden h1
    int t = threadIdx.x;
    int w = t >> 5;
    int m0 = blockIdx.x * 64;

    for (int i = t; i < 16384; i += 256) sW1[i] = W1[i];
    for (int i = t; i < 4096; i += 256)  sW2[i] = W2[i];
    for (int i = t; i < 64 * 128; i += 256) {
        int r = i >> 7, k = i & 127;
        int node = m0 + r;
        shA[r * 132 + k] = (node < N_NODES) ? g_h[node * 128 + k] : 0.f;
    }
    float prelu = pa[0];
    __syncthreads();

    // ---- layer 1: [64x128] @ [128x128]; 8 warps, each a 32x32 tile ----
    {
        int wr = w >> 2, wc = w & 3;
        wm::fragment<wm::accumulator, 16, 16, 8, float> acc[2][2];
#pragma unroll
        for (int i = 0; i < 2; i++)
#pragma unroll
            for (int j = 0; j < 2; j++) wm::fill_fragment(acc[i][j], 0.f);
        for (int k = 0; k < 128; k += 8) {
            wm::fragment<wm::matrix_a, 16, 16, 8, wm::precision::tf32, wm::row_major> a[2];
            wm::fragment<wm::matrix_b, 16, 16, 8, wm::precision::tf32, wm::row_major> b[2];
#pragma unroll
            for (int i = 0; i < 2; i++) {
                wm::load_matrix_sync(a[i], &shA[(wr * 32 + i * 16) * 132 + k], 132);
#pragma unroll
                for (int e = 0; e < a[i].num_elements; e++) a[i].x[e] = wm::__float_to_tf32(a[i].x[e]);
            }
#pragma unroll
            for (int j = 0; j < 2; j++) {
                wm::load_matrix_sync(b[j], &sW1[k * 128 + wc * 32 + j * 16], 128);
#pragma unroll
                for (int e = 0; e < b[j].num_elements; e++) b[j].x[e] = wm::__float_to_tf32(b[j].x[e]);
            }
#pragma unroll
            for (int i = 0; i < 2; i++)
#pragma unroll
                for (int j = 0; j < 2; j++)
                    wm::mma_sync(acc[i][j], a[i], b[j], acc[i][j]);
        }
#pragma unroll
        for (int i = 0; i < 2; i++)
#pragma unroll
            for (int j = 0; j < 2; j++)
                wm::store_matrix_sync(&sh1[(wr * 32 + i * 16) * 132 + wc * 32 + j * 16],
                                      acc[i][j], 132, wm::mem_row_major);
    }
    __syncthreads();
    // bias + PReLU in place
    for (int i = t; i < 64 * 128; i += 256) {
        int r = i >> 7, c = i & 127;
        float v = sh1[r * 132 + c] + b1[c];
        sh1[r * 132 + c] = v > 0.f ? v : prelu * v;
    }
    __syncthreads();
    // ---- layer 2: [64x128] @ [128x32]; 8 warps, each one 16x16 tile ----
    {
        int wr = w >> 1, wc = w & 1;
        wm::fragment<wm::accumulator, 16, 16, 8, float> acc;
        wm::fill_fragment(acc, 0.f);
        for (int k = 0; k < 128; k += 8) {
            wm::fragment<wm::matrix_a, 16, 16, 8, wm::precision::tf32, wm::row_major> a;
            wm::fragment<wm::matrix_b, 16, 16, 8, wm::precision::tf32, wm::row_major> b;
            wm::load_matrix_sync(a, &sh1[(wr * 16) * 132 + k], 132);
#pragma unroll
            for (int e = 0; e < a.num_elements; e++) a.x[e] = wm::__float_to_tf32(a.x[e]);
            wm::load_matrix_sync(b, &sW2[k * 32 + wc * 16], 32);
#pragma unroll
            for (int e = 0; e < b.num_elements; e++) b.x[e] = wm::__float_to_tf32(b.x[e]);
            wm::mma_sync(acc, a, b, acc);
        }
        wm::store_matrix_sync(&shA[(wr * 16) * 132 + wc * 16], acc, 132, wm::mem_row_major);
    }
    __syncthreads();
    // write out with b2
    for (int i = t; i < 64 * 32; i += 256) {
        int r = i >> 5, c = i & 31;
        int node = m0 + r;
        if (node < N_NODES) out[node * 32 + c] = shA[r * 132 + c] + b2[c];
    }
}

// ---------------- launch ----------------
extern "C" void kernel_launch(void* const* d_in, const int* in_sizes, int n_in,
                              void* d_out, int out_size) {
    const float*     x        = (const float*)d_in[0];
    const void*      ei       = d_in[1];
    const float*     ea       = (const float*)d_in[2];
    const float*     W_gat    = (const float*)d_in[3];
    const float*     att_src  = (const float*)d_in[4];
    const float*     att_dst  = (const float*)d_in[5];
    const float*     W_edge   = (const float*)d_in[6];
    const float*     att_edge = (const float*)d_in[7];
    const float*     bias_gat = (const float*)d_in[8];
    const float*     W1       = (const float*)d_in[9];
    const float*     b1       = (const float*)d_in[10];
    const float*     prelu_a  = (const float*)d_in[11];
    const float*     W2       = (const float*)d_in[12];
    const float*     b2       = (const float*)d_in[13];
    float*           out      = (float*)d_out;

    cudaFuncSetAttribute(k_mlp, cudaFuncAttributeMaxDynamicSharedMemorySize, MLP_SMEM);

    k_init<<<(N_NODES + 255) / 256, 256>>>((const int*)ei, W_edge, att_edge);
    k_deg<<<(NE + 255) / 256, 256>>>(ei);
    k_node<<<(N_NODES * 32 + 255) / 256, 256>>>(x, W_gat, att_src, att_dst);
    k_scan<<<SCAN_BLOCKS, 1024>>>();
    k_edge<<<(NE + 255) / 256, 256>>>(ei, ea);
    k_agg<<<(N_NODES * 32 + 255) / 256, 256>>>(bias_gat);
    k_mlp<<<(N_NODES + 63) / 64, 256, MLP_SMEM>>>(W1, b1, prelu_a, W2, b2, out);
}

// round 14
// speedup vs baseline: 1.4843x; 1.0201x over previous
#include <cuda_runtime.h>
#include <cuda_fp16.h>
#include <math.h>
#include <mma.h>

namespace wm = nvcuda::wmma;

#define N_NODES 50000
#define NE      1600000
#define HH      4
#define CC      32
#define FF      128                // HH*CC
#define NEG_SLOPE 0.2f
#define SCAN_BLOCKS 13             // ceil(50000 / 4096)
#define NODE_BLOCKS 6250           // 50000 warps / 8 warps-per-block
#define DEG_BLOCKS  6250           // 1.6M threads / 256

// ---------------- scratch (device globals; no allocations allowed) ----------------
__device__ __align__(16) __half g_xph[N_NODES * FF];    // projected features fp16 [N,128]
__device__ __align__(16) float  g_asrc[N_NODES * 4];
__device__ __align__(16) float  g_adst[N_NODES * 4];
__device__ __align__(16) float  g_aesum[N_NODES * 4];   // folded edge-att segment sum (per head)
__device__ __align__(16) int    g_deg[N_NODES];
__device__ __align__(16) int    g_rowptr[N_NODES + 4];
__device__ __align__(16) int    g_wptr[N_NODES + 4];
__device__ int    g_csrc[NE];
__device__ float4 g_calpha[NE];
__device__ __align__(16) float  g_h[N_NODES * FF];      // ELU(out+bias) hidden
__device__ float  g_M[7 * 4];                           // folded edge attention matrix
__device__ int    g_is64;                               // edge_index dtype flag
__device__ unsigned g_scanstate[SCAN_BLOCKS];

__device__ __forceinline__ float lrelu(float v) { return v > 0.f ? v : NEG_SLOPE * v; }

// index accessor that works for both int32 and int64 edge_index
__device__ __forceinline__ int ld_idx(const void* ei, int pos) {
    if (g_is64) return (int)((const long long*)ei)[pos];
    return ((const int*)ei)[pos];
}

__device__ __forceinline__ void red_add_v4(float* p, float4 v) {
    asm volatile("red.global.add.v4.f32 [%0], {%1,%2,%3,%4};"
                 :: "l"(p), "f"(v.x), "f"(v.y), "f"(v.z), "f"(v.w) : "memory");
}

// ---------------- K0: zero counters + dtype detect + fold M (merged) ----------------
__global__ void k_init(const int* __restrict__ ei_w, const float* __restrict__ W_edge,
                       const float* __restrict__ att_edge) {
    int t = blockIdx.x * blockDim.x + threadIdx.x;
    if (t < N_NODES) {
        g_deg[t] = 0;
        *(float4*)&g_aesum[t * 4] = make_float4(0.f, 0.f, 0.f, 0.f);
    }
    if (blockIdx.x == 0) {
        __shared__ int ok[2];
        int tt = threadIdx.x;
        if (tt < SCAN_BLOCKS) g_scanstate[tt] = 0u;
        if (tt < 64) {
            // int64 little-endian values < 2^31 have zero high words at odd 32-bit offsets
            int v = ei_w[2 * tt + 1];
            unsigned ball = __ballot_sync(0xFFFFFFFFu, v == 0);
            if ((tt & 31) == 0) ok[tt >> 5] = (ball == 0xFFFFFFFFu) ? 1 : 0;
        }
        __syncthreads();
        if (tt == 0) g_is64 = ok[0] & ok[1];
        if (tt < 28) {
            int k = tt >> 2, h = tt & 3;
            float s = 0.f;
            for (int c = 0; c < CC; c++) s += W_edge[k * FF + h * CC + c] * att_edge[h * CC + c];
            g_M[k * 4 + h] = s;
        }
    }
}

// ---------------- K1: fused node projection (blocks [0,NODE_BLOCKS)) + degree count ----------------
__global__ void k_node_deg(const float* __restrict__ x, const float* __restrict__ W_gat,
                           const float* __restrict__ att_src, const float* __restrict__ att_dst,
                           const void* __restrict__ ei) {
    if (blockIdx.x >= NODE_BLOCKS) {
        // ---- degree-count part ----
        int e = (blockIdx.x - NODE_BLOCKS) * blockDim.x + threadIdx.x;
        if (e < NE) {
            int dst = ld_idx(ei, NE + e);
            atomicAdd(&g_deg[dst], 1);
        }
        return;
    }
    // ---- node projection part ----
    int warp = (blockIdx.x * blockDim.x + threadIdx.x) >> 5;
    int lane = threadIdx.x & 31;
    if (warp >= N_NODES) return;
    int n = warp;
    float x0 = x[n * 3 + 0], x1 = x[n * 3 + 1], x2 = x[n * 3 + 2];
    int i0 = lane * 4;
    float v[4];
    float as = 0.f, ad = 0.f;
#pragma unroll
    for (int j = 0; j < 4; j++) {
        int i = i0 + j;
        float p = fmaf(x0, W_gat[i], fmaf(x1, W_gat[FF + i], x2 * W_gat[2 * FF + i]));
        v[j] = p;
        as = fmaf(p, att_src[i], as);
        ad = fmaf(p, att_dst[i], ad);
    }
    __half2 h0 = __floats2half2_rn(v[0], v[1]);
    __half2 h1 = __floats2half2_rn(v[2], v[3]);
    uint2 u;
    u.x = *(unsigned*)&h0;
    u.y = *(unsigned*)&h1;
    *(uint2*)&g_xph[n * FF + i0] = u;
    // reduce within each 8-lane group (one group per head)
#pragma unroll
    for (int o = 1; o < 8; o <<= 1) {
        as += __shfl_xor_sync(0xFFFFFFFFu, as, o);
        ad += __shfl_xor_sync(0xFFFFFFFFu, ad, o);
    }
    int h = lane >> 3;
    if ((lane & 7) == 0) {
        g_asrc[n * 4 + h] = as;
        g_adst[n * 4 + h] = ad;
    }
}

// ---------------- K2: single-pass decoupled-lookback exclusive scan of deg ----------------
__global__ void k_scan() {
    __shared__ int wsum[32];
    __shared__ int s_prefix;
    int bid = blockIdx.x;
    int t = threadIdx.x, lane = t & 31, w = t >> 5;
    int i0 = bid * 4096 + t * 4;
    int v0 = 0, v1 = 0, v2 = 0, v3 = 0;
    if (i0 < N_NODES) {   // N_NODES % 4 == 0 -> full int4 in-bounds
        int4 d = *(const int4*)&g_deg[i0];
        v0 = d.x; v1 = d.y; v2 = d.z; v3 = d.w;
    }
    int tsum = v0 + v1 + v2 + v3;
    int s = tsum;
#pragma unroll
    for (int o = 1; o < 32; o <<= 1) {
        int u = __shfl_up_sync(0xFFFFFFFFu, s, o);
        if (lane >= o) s += u;
    }
    if (lane == 31) wsum[w] = s;
    __syncthreads();
    if (w == 0) {
        int ws = wsum[lane];
#pragma unroll
        for (int o = 1; o < 32; o <<= 1) {
            int u = __shfl_up_sync(0xFFFFFFFFu, ws, o);
            if (lane >= o) ws += u;
        }
        wsum[lane] = ws;
    }
    __syncthreads();
    int excl = (w > 0 ? wsum[w - 1] : 0) + s - tsum;
    int agg = wsum[31];
    if (t == 0) {
        unsigned pub = (bid == 0) ? (0x80000000u | (unsigned)agg) : (0x40000000u | (unsigned)agg);
        atomicExch(&g_scanstate[bid], pub);
        int prefix = 0;
        if (bid > 0) {
            for (int j = bid - 1; j >= 0; ) {
                unsigned st;
                do { st = atomicAdd(&g_scanstate[j], 0u); } while (st == 0u);
                prefix += (int)(st & 0x3FFFFFFFu);
                if (st & 0x80000000u) break;
                j--;
            }
            atomicExch(&g_scanstate[bid], 0x80000000u | (unsigned)(prefix + agg));
        }
        s_prefix = prefix;
        if (bid == SCAN_BLOCKS - 1) g_rowptr[N_NODES] = prefix + agg;
    }
    __syncthreads();
    int base = s_prefix + excl;
    if (i0 < N_NODES) {
        int4 r;
        r.x = base; r.y = base + v0; r.z = base + v0 + v1; r.w = base + v0 + v1 + v2;
        *(int4*)&g_rowptr[i0] = r;
        *(int4*)&g_wptr[i0] = r;
    }
}

// ---------------- K3: per-edge alpha + CSR scatter + aesum accumulation ----------------
__global__ void k_edge(const void* __restrict__ ei, const float* __restrict__ ea) {
    int t = blockIdx.x * blockDim.x + threadIdx.x;
    if (t >= NE) return;
    int src = ld_idx(ei, t);
    int dst = ld_idx(ei, NE + t);
    float e[7];
#pragma unroll
    for (int k = 0; k < 7; k++) e[k] = ea[t * 7 + k];
    float4 ah4;
    float* ah = (float*)&ah4;
#pragma unroll
    for (int h = 0; h < 4; h++) {
        float s = 0.f;
#pragma unroll
        for (int k = 0; k < 7; k++) s = fmaf(e[k], g_M[k * 4 + h], s);
        ah[h] = s;
    }
    // segment-sum of folded edge attention (consumed later by k_agg self-loop)
    red_add_v4(&g_aesum[dst * 4], ah4);
    float4 as = *(const float4*)&g_asrc[src * 4];
    float4 ad = *(const float4*)&g_adst[dst * 4];
    float4 a4;
    a4.x = lrelu(as.x + ad.x + ah[0]);
    a4.y = lrelu(as.y + ad.y + ah[1]);
    a4.z = lrelu(as.z + ad.z + ah[2]);
    a4.w = lrelu(as.w + ad.w + ah[3]);
    int pos = atomicAdd(&g_wptr[dst], 1);
    g_csrc[pos] = src;
    g_calpha[pos] = a4;
}

// ---------------- K4: single-pass softmax + aggregation (shift by self-loop logit) ----------------
__global__ void k_agg(const float* __restrict__ bias) {
    int warp = (blockIdx.x * blockDim.x + threadIdx.x) >> 5;
    int lane = threadIdx.x & 31;
    if (warp >= N_NODES) return;
    int n = warp;
    int rs = g_rowptr[n], re = g_rowptr[n + 1];
    int deg = re - rs;

    // self-loop logit (same in every lane)
    float4 as4 = *(const float4*)&g_asrc[n * 4];
    float4 ad4 = *(const float4*)&g_adst[n * 4];
    float4 ae4 = *(const float4*)&g_aesum[n * 4];
    float invd = 1.0f / fmaxf((float)deg, 1.0f);
    float4 asl;
    asl.x = lrelu(as4.x + ad4.x + ae4.x * invd);
    asl.y = lrelu(as4.y + ad4.y + ae4.y * invd);
    asl.z = lrelu(as4.z + ad4.z + ae4.z * invd);
    asl.w = lrelu(as4.w + ad4.w + ae4.w * invd);

    int h = lane >> 3;
    float aslh = (h == 0) ? asl.x : (h == 1) ? asl.y : (h == 2) ? asl.z : asl.w;

    // seed with self-loop: weight exp(asl - asl) = 1
    float dh = 1.0f;
    float4 acc;
    {
        uint2 u = *(const uint2*)&g_xph[n * FF + lane * 4];
        float2 f01 = __half22float2(*(__half2*)&u.x);
        float2 f23 = __half22float2(*(__half2*)&u.y);
        acc = make_float4(f01.x, f01.y, f23.x, f23.y);
    }

    const float* abase = (const float*)g_calpha;
    int i = rs;
    // 8-wide: 8 independent gathers in flight per iteration
    for (; i + 8 <= re; i += 8) {
        int s[8];
        uint2 u[8];
        float wgt[8];
#pragma unroll
        for (int j = 0; j < 8; j++) s[j] = g_csrc[i + j];
#pragma unroll
        for (int j = 0; j < 8; j++) u[j] = *(const uint2*)&g_xph[s[j] * FF + lane * 4];
#pragma unroll
        for (int j = 0; j < 8; j++) wgt[j] = __expf(abase[(i + j) * 4 + h] - aslh);
#pragma unroll
        for (int j = 0; j < 8; j++) {
            dh += wgt[j];
            float2 f01 = __half22float2(*(__half2*)&u[j].x);
            float2 f23 = __half22float2(*(__half2*)&u[j].y);
            acc.x += wgt[j] * f01.x; acc.y += wgt[j] * f01.y;
            acc.z += wgt[j] * f23.x; acc.w += wgt[j] * f23.y;
        }
    }
    for (; i < re; i++) {
        int s0 = g_csrc[i];
        float w0 = __expf(abase[i * 4 + h] - aslh);
        dh += w0;
        uint2 u0 = *(const uint2*)&g_xph[s0 * FF + lane * 4];
        float2 a01 = __half22float2(*(__half2*)&u0.x), a23 = __half22float2(*(__half2*)&u0.y);
        acc.x += w0 * a01.x; acc.y += w0 * a01.y;
        acc.z += w0 * a23.x; acc.w += w0 * a23.y;
    }
    float ih = 1.0f / dh;

    // ELU(out + bias)
    float4 b = *(const float4*)&bias[lane * 4];
    float r0 = acc.x * ih + b.x, r1 = acc.y * ih + b.y;
    float r2 = acc.z * ih + b.z, r3 = acc.w * ih + b.w;
    r0 = r0 > 0.f ? r0 : expm1f(r0);
    r1 = r1 > 0.f ? r1 : expm1f(r1);
    r2 = r2 > 0.f ? r2 : expm1f(r2);
    r3 = r3 > 0.f ? r3 : expm1f(r3);
    *(float4*)&g_h[n * FF + lane * 4] = make_float4(r0, r1, r2, r3);
}

// ---------------- K5: fused MLP via tf32 tensor cores ----------------
// smem: sW1[128][128] + sW2[128][32] + shA[64][132] + sh1[64][132]
#define MLP_SMEM (16384*4 + 4096*4 + 8448*4 + 8448*4)
__global__ void k_mlp(const float* __restrict__ W1, const float* __restrict__ b1,
                      const float* __restrict__ pa, const float* __restrict__ W2,
                      const float* __restrict__ b2, float* __restrict__ out) {
    extern __shared__ float smem[];
    float* sW1 = smem;              // [128][128]
    float* sW2 = sW1 + 16384;       // [128][32]
    float* shA = sW2 + 4096;        // [64][132]  input h (then layer-2 output)
    float* sh1 = shA + 8448;        // [64][132]  hidden h1
    int t = threadIdx.x;
    int w = t >> 5;
    int m0 = blockIdx.x * 64;

    for (int i = t; i < 16384; i += 256) sW1[i] = W1[i];
    for (int i = t; i < 4096; i += 256)  sW2[i] = W2[i];
    for (int i = t; i < 64 * 128; i += 256) {
        int r = i >> 7, k = i & 127;
        int node = m0 + r;
        shA[r * 132 + k] = (node < N_NODES) ? g_h[node * 128 + k] : 0.f;
    }
    float prelu = pa[0];
    __syncthreads();

    // ---- layer 1: [64x128] @ [128x128]; 8 warps, each a 32x32 tile ----
    {
        int wr = w >> 2, wc = w & 3;
        wm::fragment<wm::accumulator, 16, 16, 8, float> acc[2][2];
#pragma unroll
        for (int i = 0; i < 2; i++)
#pragma unroll
            for (int j = 0; j < 2; j++) wm::fill_fragment(acc[i][j], 0.f);
        for (int k = 0; k < 128; k += 8) {
            wm::fragment<wm::matrix_a, 16, 16, 8, wm::precision::tf32, wm::row_major> a[2];
            wm::fragment<wm::matrix_b, 16, 16, 8, wm::precision::tf32, wm::row_major> b[2];
#pragma unroll
            for (int i = 0; i < 2; i++) {
                wm::load_matrix_sync(a[i], &shA[(wr * 32 + i * 16) * 132 + k], 132);
#pragma unroll
                for (int e = 0; e < a[i].num_elements; e++) a[i].x[e] = wm::__float_to_tf32(a[i].x[e]);
            }
#pragma unroll
            for (int j = 0; j < 2; j++) {
                wm::load_matrix_sync(b[j], &sW1[k * 128 + wc * 32 + j * 16], 128);
#pragma unroll
                for (int e = 0; e < b[j].num_elements; e++) b[j].x[e] = wm::__float_to_tf32(b[j].x[e]);
            }
#pragma unroll
            for (int i = 0; i < 2; i++)
#pragma unroll
                for (int j = 0; j < 2; j++)
                    wm::mma_sync(acc[i][j], a[i], b[j], acc[i][j]);
        }
#pragma unroll
        for (int i = 0; i < 2; i++)
#pragma unroll
            for (int j = 0; j < 2; j++)
                wm::store_matrix_sync(&sh1[(wr * 32 + i * 16) * 132 + wc * 32 + j * 16],
                                      acc[i][j], 132, wm::mem_row_major);
    }
    __syncthreads();
    // bias + PReLU in place
    for (int i = t; i < 64 * 128; i += 256) {
        int r = i >> 7, c = i & 127;
        float v = sh1[r * 132 + c] + b1[c];
        sh1[r * 132 + c] = v > 0.f ? v : prelu * v;
    }
    __syncthreads();
    // ---- layer 2: [64x128] @ [128x32]; 8 warps, each one 16x16 tile ----
    {
        int wr = w >> 1, wc = w & 1;
        wm::fragment<wm::accumulator, 16, 16, 8, float> acc;
        wm::fill_fragment(acc, 0.f);
        for (int k = 0; k < 128; k += 8) {
            wm::fragment<wm::matrix_a, 16, 16, 8, wm::precision::tf32, wm::row_major> a;
            wm::fragment<wm::matrix_b, 16, 16, 8, wm::precision::tf32, wm::row_major> b;
            wm::load_matrix_sync(a, &sh1[(wr * 16) * 132 + k], 132);
#pragma unroll
            for (int e = 0; e < a.num_elements; e++) a.x[e] = wm::__float_to_tf32(a.x[e]);
            wm::load_matrix_sync(b, &sW2[k * 32 + wc * 16], 32);
#pragma unroll
            for (int e = 0; e < b.num_elements; e++) b.x[e] = wm::__float_to_tf32(b.x[e]);
            wm::mma_sync(acc, a, b, acc);
        }
        wm::store_matrix_sync(&shA[(wr * 16) * 132 + wc * 16], acc, 132, wm::mem_row_major);
    }
    __syncthreads();
    // write out with b2
    for (int i = t; i < 64 * 32; i += 256) {
        int r = i >> 5, c = i & 31;
        int node = m0 + r;
        if (node < N_NODES) out[node * 32 + c] = shA[r * 132 + c] + b2[c];
    }
}

// ---------------- launch ----------------
extern "C" void kernel_launch(void* const* d_in, const int* in_sizes, int n_in,
                              void* d_out, int out_size) {
    const float*     x        = (const float*)d_in[0];
    const void*      ei       = d_in[1];
    const float*     ea       = (const float*)d_in[2];
    const float*     W_gat    = (const float*)d_in[3];
    const float*     att_src  = (const float*)d_in[4];
    const float*     att_dst  = (const float*)d_in[5];
    const float*     W_edge   = (const float*)d_in[6];
    const float*     att_edge = (const float*)d_in[7];
    const float*     bias_gat = (const float*)d_in[8];
    const float*     W1       = (const float*)d_in[9];
    const float*     b1       = (const float*)d_in[10];
    const float*     prelu_a  = (const float*)d_in[11];
    const float*     W2       = (const float*)d_in[12];
    const float*     b2       = (const float*)d_in[13];
    float*           out      = (float*)d_out;

    cudaFuncSetAttribute(k_mlp, cudaFuncAttributeMaxDynamicSharedMemorySize, MLP_SMEM);

    k_init<<<(N_NODES + 255) / 256, 256>>>((const int*)ei, W_edge, att_edge);
    k_node_deg<<<NODE_BLOCKS + DEG_BLOCKS, 256>>>(x, W_gat, att_src, att_dst, ei);
    k_scan<<<SCAN_BLOCKS, 1024>>>();
    k_edge<<<(NE + 255) / 256, 256>>>(ei, ea);
    k_agg<<<(N_NODES * 32 + 255) / 256, 256>>>(bias_gat);
    k_mlp<<<(N_NODES + 63) / 64, 256, MLP_SMEM>>>(W1, b1, prelu_a, W2, b2, out);
}